// round 1
// baseline (speedup 1.0000x reference)
#include <cuda_runtime.h>
#include <cuda_bf16.h>
#include <math.h>

// ---------------- problem constants ----------------
#define SEQ     2048
#define DMODEL  512
#define DINNER  1024
#define DSTATE  64
#define DTRANK  32
#define DCONV   4
#define XZCOLS  (2*DINNER)          // 2048
#define DBCCOLS (DTRANK + 2*DSTATE) // 160

// ---------------- scratch (device globals; no allocation) ----------------
__device__ float g_xn [SEQ*DMODEL];        // layernorm out             [t][d]
__device__ float g_xz [SEQ*XZCOLS];        // xn @ Win^T                [t][e]
__device__ float g_xi [SEQ*DINNER];        // conv+silu                 [t][c]
__device__ float g_xiT[DINNER*SEQ];        // transposed                [c][t]
__device__ float g_zsT[DINNER*SEQ];        // silu(z) transposed        [c][t]
__device__ float g_dbc[SEQ*DBCCOLS];       // xi @ Wx^T                 [t][r]
__device__ float g_dT [DINNER*SEQ];        // delta transposed          [c][t]
__device__ float g_yT [DINNER*SEQ];        // scan output (final y)     [c][t]

// ---------------- helpers ----------------
__device__ __forceinline__ float siluf(float x) { return x / (1.0f + __expf(-x)); }
__device__ __forceinline__ float softplusf(float x) {
    return (x > 15.0f) ? x : log1pf(__expf(x));
}

// ---------------- LayerNorm: one block per token ----------------
__global__ void ln_kernel(const float* __restrict__ x,
                          const float* __restrict__ g,
                          const float* __restrict__ b,
                          float* __restrict__ xn)
{
    int t   = blockIdx.x;
    int tid = threadIdx.x;             // 256 threads, 2 elems each
    const float* xr = x + t * DMODEL;
    float2 v = *(const float2*)&xr[tid * 2];
    float s = v.x + v.y;
    float q = v.x * v.x + v.y * v.y;
    #pragma unroll
    for (int o = 16; o > 0; o >>= 1) {
        s += __shfl_xor_sync(0xffffffffu, s, o);
        q += __shfl_xor_sync(0xffffffffu, q, o);
    }
    __shared__ float ss[8], qq[8];
    int lane = tid & 31, w = tid >> 5;
    if (lane == 0) { ss[w] = s; qq[w] = q; }
    __syncthreads();
    s = 0.f; q = 0.f;
    #pragma unroll
    for (int i = 0; i < 8; i++) { s += ss[i]; q += qq[i]; }
    float mu  = s * (1.0f / DMODEL);
    float var = q * (1.0f / DMODEL) - mu * mu;
    float r   = rsqrtf(var + 1e-5f);
    float2 gg = *(const float2*)&g[tid * 2];
    float2 bb = *(const float2*)&b[tid * 2];
    float2 o;
    o.x = (v.x - mu) * r * gg.x + bb.x;
    o.y = (v.y - mu) * r * gg.y + bb.y;
    *(float2*)&xn[t * DMODEL + tid * 2] = o;
}

// ---------------- Generic tiled GEMM ----------------
// C[m][n] = sum_k A(m,k) * B[n][k]   (B always row-major [N][K])
// ATRANS=false: A row-major [M][K], lda = row stride
// ATRANS=true : A stored [K][M], A(m,k) = A[k*lda + m]
// epi: 0 none; 1 softplus(acc + ep1[m]); 2 acc + ep1[m*ldc + n]
template<bool ATRANS>
__global__ __launch_bounds__(256)
void gemm64(const float* __restrict__ A, int lda,
            const float* __restrict__ B, int ldb,
            float* __restrict__ C, int ldc,
            int M, int N, int K,
            int epi, const float* __restrict__ ep1)
{
    const int BM = 64, BN = 64, BK = 16;
    __shared__ __align__(16) float As[BK][BM];
    __shared__ __align__(16) float Bs[BK][BN];

    int tid = threadIdx.x;
    int bm = blockIdx.y * BM, bn = blockIdx.x * BN;

    int arow = tid >> 2;            // 0..63
    int akq  = (tid & 3) * 4;       // 0,4,8,12
    int am0  = (tid & 15) * 4;      // ATRANS path
    int ak   = tid >> 4;

    int ty = tid >> 4, tx = tid & 15;
    float acc[4][4] = {};

    for (int k0 = 0; k0 < K; k0 += BK) {
        if (!ATRANS) {
            float4 a = *(const float4*)&A[(bm + arow) * lda + k0 + akq];
            As[akq + 0][arow] = a.x; As[akq + 1][arow] = a.y;
            As[akq + 2][arow] = a.z; As[akq + 3][arow] = a.w;
        } else {
            float4 a = *(const float4*)&A[(k0 + ak) * lda + bm + am0];
            *(float4*)&As[ak][am0] = a;
        }
        {
            int nrow = bn + arow;
            float4 bv = make_float4(0.f, 0.f, 0.f, 0.f);
            if (nrow < N) bv = *(const float4*)&B[nrow * ldb + k0 + akq];
            Bs[akq + 0][arow] = bv.x; Bs[akq + 1][arow] = bv.y;
            Bs[akq + 2][arow] = bv.z; Bs[akq + 3][arow] = bv.w;
        }
        __syncthreads();
        #pragma unroll
        for (int kk = 0; kk < BK; kk++) {
            float4 av = *(const float4*)&As[kk][ty * 4];
            float4 bv = *(const float4*)&Bs[kk][tx * 4];
            float ar[4] = {av.x, av.y, av.z, av.w};
            float br[4] = {bv.x, bv.y, bv.z, bv.w};
            #pragma unroll
            for (int i = 0; i < 4; i++)
                #pragma unroll
                for (int j = 0; j < 4; j++)
                    acc[i][j] += ar[i] * br[j];
        }
        __syncthreads();
    }

    #pragma unroll
    for (int i = 0; i < 4; i++) {
        int m = bm + ty * 4 + i;
        #pragma unroll
        for (int j = 0; j < 4; j++) {
            int n = bn + tx * 4 + j;
            if (n < N) {
                float v = acc[i][j];
                if (epi == 1)      v = softplusf(v + ep1[m]);
                else if (epi == 2) v = v + ep1[m * ldc + n];
                C[m * ldc + n] = v;
            }
        }
    }
}

// ---------------- depthwise conv (width 4, causal) + silu + transposes ----------------
// reads g_xz; writes g_xi[t][c], g_xiT[c][t], g_zsT[c][t]
__global__ __launch_bounds__(256)
void conv_kernel(const float* __restrict__ cw, const float* __restrict__ cb)
{
    __shared__ float sxz[35][33];
    __shared__ float sxi[32][33];
    __shared__ float szs[32][33];
    int t0 = blockIdx.x * 32, c0 = blockIdx.y * 32;
    int tid = threadIdx.x;

    for (int i = tid; i < 35 * 32; i += 256) {
        int r = i >> 5, c = i & 31;
        int gt = t0 + r - 3;
        sxz[r][c] = (gt >= 0) ? g_xz[gt * XZCOLS + c0 + c] : 0.0f;
    }
    for (int i = tid; i < 32 * 32; i += 256) {
        int r = i >> 5, c = i & 31;
        float z = g_xz[(t0 + r) * XZCOLS + DINNER + c0 + c];
        szs[r][c] = siluf(z);
    }
    __syncthreads();

    int cl = tid & 31, tq = tid >> 5;
    float4 w = *(const float4*)&cw[(c0 + cl) * 4];
    float bb = cb[c0 + cl];
    #pragma unroll
    for (int s = 0; s < 4; s++) {
        int tl = tq + s * 8;
        float v = sxz[tl + 0][cl] * w.x + sxz[tl + 1][cl] * w.y +
                  sxz[tl + 2][cl] * w.z + sxz[tl + 3][cl] * w.w + bb;
        v = siluf(v);
        g_xi[(t0 + tl) * DINNER + c0 + cl] = v;
        sxi[tl][cl] = v;
    }
    __syncthreads();

    int tl2 = tid & 31, cq = tid >> 5;
    #pragma unroll
    for (int s = 0; s < 4; s++) {
        int cl2 = cq + s * 8;
        g_xiT[(c0 + cl2) * SEQ + t0 + tl2] = sxi[tl2][cl2];
        g_zsT[(c0 + cl2) * SEQ + t0 + tl2] = szs[tl2][cl2];
    }
}

// ---------------- selective scan: one warp per channel ----------------
// h[d][n] recurrence over t; 2 states per lane (n = lane, lane+32).
// B[t][n] = dbc[t][32+n], C[t][n] = dbc[t][96+n], shared across 8 warps via smem.
// writes final y^T[d][t] = (scan_y + Dp[d]*xi[t,d]) * silu(z[t,d])
__global__ __launch_bounds__(256)
void scan_kernel(const float* __restrict__ A_log, const float* __restrict__ Dp)
{
    __shared__ __align__(16) float sBC[32][128];
    int tid = threadIdx.x, lane = tid & 31, w = tid >> 5;
    int d = blockIdx.x * 8 + w;

    float A0 = -expf(A_log[d * DSTATE + lane]);
    float A1 = -expf(A_log[d * DSTATE + 32 + lane]);
    float Dpd = Dp[d];
    float h0 = 0.f, h1 = 0.f;

    const float* dT = g_dT  + d * SEQ;
    const float* xT = g_xiT + d * SEQ;
    const float* zT = g_zsT + d * SEQ;
    float*       yT = g_yT  + d * SEQ;

    for (int t0 = 0; t0 < SEQ; t0 += 32) {
        __syncthreads();
        for (int i = tid; i < 1024; i += 256) {
            int r = i >> 5, cq = (i & 31) << 2;
            *(float4*)&sBC[r][cq] =
                *(const float4*)&g_dbc[(t0 + r) * DBCCOLS + DTRANK + cq];
        }
        __syncthreads();

        float myD = dT[t0 + lane];
        float myX = xT[t0 + lane];
        float myZ = zT[t0 + lane];
        float yout = 0.f;

        #pragma unroll 4
        for (int i = 0; i < 32; i++) {
            float du = __shfl_sync(0xffffffffu, myD, i);
            float xv = __shfl_sync(0xffffffffu, myX, i);
            float dux = du * xv;
            h0 = __expf(du * A0) * h0 + dux * sBC[i][lane];
            h1 = __expf(du * A1) * h1 + dux * sBC[i][32 + lane];
            float acc = h0 * sBC[i][64 + lane] + h1 * sBC[i][96 + lane];
            #pragma unroll
            for (int o = 16; o > 0; o >>= 1)
                acc += __shfl_xor_sync(0xffffffffu, acc, o);
            if (lane == i) yout = acc;
        }
        yT[t0 + lane] = (yout + Dpd * myX) * myZ;
    }
}

// ---------------- launcher ----------------
extern "C" void kernel_launch(void* const* d_in, const int* in_sizes, int n_in,
                              void* d_out, int out_size)
{
    const float* x      = (const float*)d_in[0];
    const float* ln_g   = (const float*)d_in[1];
    const float* ln_b   = (const float*)d_in[2];
    const float* Win    = (const float*)d_in[3];
    const float* conv_w = (const float*)d_in[4];
    const float* conv_b = (const float*)d_in[5];
    const float* Wx     = (const float*)d_in[6];
    const float* Wdt    = (const float*)d_in[7];
    const float* bdt    = (const float*)d_in[8];
    const float* A_log  = (const float*)d_in[9];
    const float* Dp     = (const float*)d_in[10];
    const float* Wout   = (const float*)d_in[11];
    float* out = (float*)d_out;

    float *p_xn, *p_xz, *p_xi, *p_xiT, *p_dbc, *p_dT, *p_yT;
    cudaGetSymbolAddress((void**)&p_xn,  g_xn);
    cudaGetSymbolAddress((void**)&p_xz,  g_xz);
    cudaGetSymbolAddress((void**)&p_xi,  g_xi);
    cudaGetSymbolAddress((void**)&p_xiT, g_xiT);
    cudaGetSymbolAddress((void**)&p_dbc, g_dbc);
    cudaGetSymbolAddress((void**)&p_dT,  g_dT);
    cudaGetSymbolAddress((void**)&p_yT,  g_yT);

    // 1. LayerNorm
    ln_kernel<<<SEQ, 256>>>(x, ln_g, ln_b, p_xn);

    // 2. xz = xn @ Win^T   [2048 x 2048 x 512]
    gemm64<false><<<dim3(XZCOLS / 64, SEQ / 64), 256>>>(
        p_xn, DMODEL, Win, DMODEL, p_xz, XZCOLS,
        SEQ, XZCOLS, DMODEL, 0, nullptr);

    // 3. conv + silu + transposes
    conv_kernel<<<dim3(SEQ / 32, DINNER / 32), 256>>>(conv_w, conv_b);

    // 4. dbc = xi @ Wx^T   [2048 x 160 x 1024]
    gemm64<false><<<dim3((DBCCOLS + 63) / 64, SEQ / 64), 256>>>(
        p_xi, DINNER, Wx, DINNER, p_dbc, DBCCOLS,
        SEQ, DBCCOLS, DINNER, 0, nullptr);

    // 5. delta^T[d][t] = softplus(Wdt[d,:] . dt[t,:] + bdt[d])   [1024 x 2048 x 32]
    //    A = Wdt (lda=32), B = dbc columns [0,32) (ldb=160)
    gemm64<false><<<dim3(SEQ / 64, DINNER / 64), 256>>>(
        Wdt, DTRANK, p_dbc, DBCCOLS, p_dT, SEQ,
        DINNER, SEQ, DTRANK, 1, bdt);

    // 6. selective scan -> y^T (with +Dp*xi and *silu(z) fused)
    scan_kernel<<<DINNER / 8, 256>>>(A_log, Dp);

    // 7. out = y @ Wout^T + x   [2048 x 512 x 1024], A = y^T (transposed layout)
    gemm64<true><<<dim3(DMODEL / 64, SEQ / 64), 256>>>(
        p_yT, SEQ, Wout, DINNER, out, DMODEL,
        SEQ, DMODEL, DINNER, 2, x);
}

// round 2
// speedup vs baseline: 1.1094x; 1.1094x over previous
#include <cuda_runtime.h>
#include <cuda_bf16.h>
#include <math.h>

// ---------------- problem constants ----------------
#define SEQ     2048
#define DMODEL  512
#define DINNER  1024
#define DSTATE  64
#define DTRANK  32
#define DCONV   4
#define XZCOLS  (2*DINNER)          // 2048
#define DBCCOLS (DTRANK + 2*DSTATE) // 160
#define NSPLIT  4

// ---------------- scratch (device globals; no allocation) ----------------
__device__ float g_xn  [SEQ*DMODEL];          // layernorm out        [t][d]
__device__ float g_xz  [SEQ*XZCOLS];          // xn @ Win^T           [t][e]
__device__ float g_xi  [SEQ*DINNER];          // conv+silu            [t][c]
__device__ float g_xiT [DINNER*SEQ];          // transposed           [c][t]
__device__ float g_zsT [DINNER*SEQ];          // silu(z) transposed   [c][t]
__device__ float g_dbcp[NSPLIT*SEQ*DBCCOLS];  // split-K partials
__device__ float g_dbc [SEQ*DBCCOLS];         // xi @ Wx^T            [t][r]
__device__ float g_yT  [DINNER*SEQ];          // scan output (y)      [c][t]

// ---------------- helpers ----------------
__device__ __forceinline__ float siluf(float x) { return x / (1.0f + __expf(-x)); }
__device__ __forceinline__ float softplusf(float x) {
    return (x > 15.0f) ? x : log1pf(__expf(x));
}

// ---------------- LayerNorm: one block per token ----------------
__global__ void ln_kernel(const float* __restrict__ x,
                          const float* __restrict__ g,
                          const float* __restrict__ b,
                          float* __restrict__ xn)
{
    int t   = blockIdx.x;
    int tid = threadIdx.x;             // 256 threads, 2 elems each
    const float* xr = x + t * DMODEL;
    float2 v = *(const float2*)&xr[tid * 2];
    float s = v.x + v.y;
    float q = v.x * v.x + v.y * v.y;
    #pragma unroll
    for (int o = 16; o > 0; o >>= 1) {
        s += __shfl_xor_sync(0xffffffffu, s, o);
        q += __shfl_xor_sync(0xffffffffu, q, o);
    }
    __shared__ float ss[8], qq[8];
    int lane = tid & 31, w = tid >> 5;
    if (lane == 0) { ss[w] = s; qq[w] = q; }
    __syncthreads();
    s = 0.f; q = 0.f;
    #pragma unroll
    for (int i = 0; i < 8; i++) { s += ss[i]; q += qq[i]; }
    float mu  = s * (1.0f / DMODEL);
    float var = q * (1.0f / DMODEL) - mu * mu;
    float r   = rsqrtf(var + 1e-5f);
    float2 gg = *(const float2*)&g[tid * 2];
    float2 bb = *(const float2*)&b[tid * 2];
    float2 o;
    o.x = (v.x - mu) * r * gg.x + bb.x;
    o.y = (v.y - mu) * r * gg.y + bb.y;
    *(float2*)&xn[t * DMODEL + tid * 2] = o;
}

// ---------------- big SGEMM: BM=128, BK=8, double buffered ----------------
// C[m][n] = sum_k A(m,k)*B[n][k]; B row-major [N][K].
// ATRANS=false: A row-major [M][K]. ATRANS=true: A stored [K][M].
// RESID: C += resid (same layout as C). All dims assumed to divide tiles.
template<int BN, int TN, bool ATRANS, bool RESID>
__global__ __launch_bounds__(256, 2)
void sgemm(const float* __restrict__ A, int lda,
           const float* __restrict__ B, int ldb,
           float* __restrict__ C, int ldc,
           int K, const float* __restrict__ resid)
{
    constexpr int BM = 128, BK = 8, TM = 8;
    __shared__ __align__(16) float As[2][BK][BM + 4];
    __shared__ __align__(16) float Bs[2][BK][BN + 4];

    const int tid = threadIdx.x;
    const int bm = blockIdx.y * BM;
    const int bn = blockIdx.x * BN;

    const int tx = tid & 15;   // BN/TN == 16 for both configs
    const int ty = tid >> 4;

    // A load coords
    const int a_row = tid >> 1;            // !ATRANS: 0..127
    const int a_kq  = (tid & 1) << 2;      // 0 or 4
    const int at_k  = tid >> 5;            // ATRANS: 0..7
    const int at_m  = (tid & 31) << 2;     // 0..124

    // B load coords
    const int b_row = (BN == 128) ? (tid >> 1) : (tid >> 2);
    const int b_kq  = (BN == 128) ? ((tid & 1) << 2) : ((tid & 3) << 1);

    float acc[TM][TN];
    #pragma unroll
    for (int i = 0; i < TM; i++)
        #pragma unroll
        for (int j = 0; j < TN; j++) acc[i][j] = 0.0f;

    float4 ra; float4 rb4; float2 rb2;

    // ---- prologue: load k-tile 0 ----
    if (!ATRANS) ra = *(const float4*)&A[(bm + a_row) * lda + a_kq];
    else         ra = *(const float4*)&A[(at_k) * lda + bm + at_m];
    if (BN == 128) rb4 = *(const float4*)&B[(bn + b_row) * ldb + b_kq];
    else           rb2 = *(const float2*)&B[(bn + b_row) * ldb + b_kq];

    if (!ATRANS) {
        As[0][a_kq + 0][a_row] = ra.x; As[0][a_kq + 1][a_row] = ra.y;
        As[0][a_kq + 2][a_row] = ra.z; As[0][a_kq + 3][a_row] = ra.w;
    } else {
        *(float4*)&As[0][at_k][at_m] = ra;
    }
    if (BN == 128) {
        Bs[0][b_kq + 0][b_row] = rb4.x; Bs[0][b_kq + 1][b_row] = rb4.y;
        Bs[0][b_kq + 2][b_row] = rb4.z; Bs[0][b_kq + 3][b_row] = rb4.w;
    } else {
        Bs[0][b_kq + 0][b_row] = rb2.x; Bs[0][b_kq + 1][b_row] = rb2.y;
    }
    __syncthreads();

    int cur = 0;
    for (int k0 = 0; k0 < K; k0 += BK) {
        const int kn = k0 + BK;
        const bool has = kn < K;
        if (has) {
            if (!ATRANS) ra = *(const float4*)&A[(bm + a_row) * lda + kn + a_kq];
            else         ra = *(const float4*)&A[(kn + at_k) * lda + bm + at_m];
            if (BN == 128) rb4 = *(const float4*)&B[(bn + b_row) * ldb + kn + b_kq];
            else           rb2 = *(const float2*)&B[(bn + b_row) * ldb + kn + b_kq];
        }
        #pragma unroll
        for (int kk = 0; kk < BK; kk++) {
            float4 a0 = *(const float4*)&As[cur][kk][ty * TM];
            float4 a1 = *(const float4*)&As[cur][kk][ty * TM + 4];
            float rA[8] = {a0.x, a0.y, a0.z, a0.w, a1.x, a1.y, a1.z, a1.w};
            float rB[TN];
            if (TN == 8) {
                float4 b0 = *(const float4*)&Bs[cur][kk][tx * TN];
                float4 b1 = *(const float4*)&Bs[cur][kk][tx * TN + 4];
                rB[0] = b0.x; rB[1] = b0.y; rB[2] = b0.z; rB[3] = b0.w;
                rB[4] = b1.x; rB[5] = b1.y; rB[6] = b1.z; rB[7] = b1.w;
            } else {
                float4 b0 = *(const float4*)&Bs[cur][kk][tx * TN];
                rB[0] = b0.x; rB[1] = b0.y; rB[2] = b0.z; rB[3] = b0.w;
            }
            #pragma unroll
            for (int i = 0; i < TM; i++)
                #pragma unroll
                for (int j = 0; j < TN; j++)
                    acc[i][j] = fmaf(rA[i], rB[j], acc[i][j]);
        }
        if (has) {
            cur ^= 1;
            if (!ATRANS) {
                As[cur][a_kq + 0][a_row] = ra.x; As[cur][a_kq + 1][a_row] = ra.y;
                As[cur][a_kq + 2][a_row] = ra.z; As[cur][a_kq + 3][a_row] = ra.w;
            } else {
                *(float4*)&As[cur][at_k][at_m] = ra;
            }
            if (BN == 128) {
                Bs[cur][b_kq + 0][b_row] = rb4.x; Bs[cur][b_kq + 1][b_row] = rb4.y;
                Bs[cur][b_kq + 2][b_row] = rb4.z; Bs[cur][b_kq + 3][b_row] = rb4.w;
            } else {
                Bs[cur][b_kq + 0][b_row] = rb2.x; Bs[cur][b_kq + 1][b_row] = rb2.y;
            }
            __syncthreads();
        }
    }

    // ---- epilogue ----
    #pragma unroll
    for (int i = 0; i < TM; i++) {
        int m = bm + ty * TM + i;
        #pragma unroll
        for (int j = 0; j < TN; j += 4) {
            int n = bn + tx * TN + j;
            float4 v = make_float4(acc[i][j], acc[i][j+1], acc[i][j+2], acc[i][j+3]);
            if (RESID) {
                float4 r = *(const float4*)&resid[m * ldc + n];
                v.x += r.x; v.y += r.y; v.z += r.z; v.w += r.w;
            }
            *(float4*)&C[m * ldc + n] = v;
        }
    }
}

// ---------------- G2: 64x64 tile, split-K over blockIdx.z ----------------
// Cpart[z][m][n] = sum over k in [z*Ks,(z+1)*Ks) of A[m][k]*B[n][k]
__global__ __launch_bounds__(256)
void gemm64_splitk(const float* __restrict__ A, int lda,
                   const float* __restrict__ B, int ldb,
                   float* __restrict__ Cpart, int ldc,
                   int M, int N, int Ks)
{
    const int BM = 64, BN = 64, BK = 16;
    __shared__ __align__(16) float As[BK][BM];
    __shared__ __align__(16) float Bs[BK][BN];

    int tid = threadIdx.x;
    int bm = blockIdx.y * BM, bn = blockIdx.x * BN;
    int z = blockIdx.z;
    float* C = Cpart + (size_t)z * M * ldc;
    int kbeg = z * Ks, kend = kbeg + Ks;

    int arow = tid >> 2;
    int akq  = (tid & 3) * 4;
    int ty = tid >> 4, tx = tid & 15;
    float acc[4][4] = {};

    for (int k0 = kbeg; k0 < kend; k0 += BK) {
        {
            float4 a = *(const float4*)&A[(bm + arow) * lda + k0 + akq];
            As[akq + 0][arow] = a.x; As[akq + 1][arow] = a.y;
            As[akq + 2][arow] = a.z; As[akq + 3][arow] = a.w;
        }
        {
            int nrow = bn + arow;
            float4 bv = make_float4(0.f, 0.f, 0.f, 0.f);
            if (nrow < N) bv = *(const float4*)&B[nrow * ldb + k0 + akq];
            Bs[akq + 0][arow] = bv.x; Bs[akq + 1][arow] = bv.y;
            Bs[akq + 2][arow] = bv.z; Bs[akq + 3][arow] = bv.w;
        }
        __syncthreads();
        #pragma unroll
        for (int kk = 0; kk < BK; kk++) {
            float4 av = *(const float4*)&As[kk][ty * 4];
            float4 bv = *(const float4*)&Bs[kk][tx * 4];
            float ar[4] = {av.x, av.y, av.z, av.w};
            float br[4] = {bv.x, bv.y, bv.z, bv.w};
            #pragma unroll
            for (int i = 0; i < 4; i++)
                #pragma unroll
                for (int j = 0; j < 4; j++)
                    acc[i][j] = fmaf(ar[i], br[j], acc[i][j]);
        }
        __syncthreads();
    }

    #pragma unroll
    for (int i = 0; i < 4; i++) {
        int m = bm + ty * 4 + i;
        #pragma unroll
        for (int j = 0; j < 4; j++) {
            int n = bn + tx * 4 + j;
            if (n < N) C[m * ldc + n] = acc[i][j];
        }
    }
}

// deterministic reduce of the 4 split-K partials (float4 per thread)
__global__ void reduce4_kernel()
{
    int i = (blockIdx.x * 256 + threadIdx.x) * 4;   // float index
    const int TOT = SEQ * DBCCOLS;
    float4 a = *(const float4*)&g_dbcp[0 * TOT + i];
    float4 b = *(const float4*)&g_dbcp[1 * TOT + i];
    float4 c = *(const float4*)&g_dbcp[2 * TOT + i];
    float4 d = *(const float4*)&g_dbcp[3 * TOT + i];
    float4 o;
    o.x = (a.x + b.x) + (c.x + d.x);
    o.y = (a.y + b.y) + (c.y + d.y);
    o.z = (a.z + b.z) + (c.z + d.z);
    o.w = (a.w + b.w) + (c.w + d.w);
    *(float4*)&g_dbc[i] = o;
}

// ---------------- depthwise conv (width 4, causal) + silu + transposes ----------------
__global__ __launch_bounds__(256)
void conv_kernel(const float* __restrict__ cw, const float* __restrict__ cb)
{
    __shared__ float sxz[35][33];
    __shared__ float sxi[32][33];
    __shared__ float szs[32][33];
    int t0 = blockIdx.x * 32, c0 = blockIdx.y * 32;
    int tid = threadIdx.x;

    for (int i = tid; i < 35 * 32; i += 256) {
        int r = i >> 5, c = i & 31;
        int gt = t0 + r - 3;
        sxz[r][c] = (gt >= 0) ? g_xz[gt * XZCOLS + c0 + c] : 0.0f;
    }
    for (int i = tid; i < 32 * 32; i += 256) {
        int r = i >> 5, c = i & 31;
        float z = g_xz[(t0 + r) * XZCOLS + DINNER + c0 + c];
        szs[r][c] = siluf(z);
    }
    __syncthreads();

    int cl = tid & 31, tq = tid >> 5;
    float4 w = *(const float4*)&cw[(c0 + cl) * 4];
    float bb = cb[c0 + cl];
    #pragma unroll
    for (int s = 0; s < 4; s++) {
        int tl = tq + s * 8;
        float v = sxz[tl + 0][cl] * w.x + sxz[tl + 1][cl] * w.y +
                  sxz[tl + 2][cl] * w.z + sxz[tl + 3][cl] * w.w + bb;
        v = siluf(v);
        g_xi[(t0 + tl) * DINNER + c0 + cl] = v;
        sxi[tl][cl] = v;
    }
    __syncthreads();

    int tl2 = tid & 31, cq = tid >> 5;
    #pragma unroll
    for (int s = 0; s < 4; s++) {
        int cl2 = cq + s * 8;
        g_xiT[(c0 + cl2) * SEQ + t0 + tl2] = sxi[tl2][cl2];
        g_zsT[(c0 + cl2) * SEQ + t0 + tl2] = szs[tl2][cl2];
    }
}

// ---------------- selective scan with fused delta GEMV + softplus ----------------
// One warp per channel d. Stages full dbc rows [t0..t0+32) x 160 in smem.
// delta(d,t) = softplus(dot(Wdt[d,:], dbc[t,0:32]) + bdt[d])  computed per lane.
// h recurrence over 64 states (2 per lane); y reduced via shfl-xor.
__global__ __launch_bounds__(256)
void scan_kernel(const float* __restrict__ Wdt, const float* __restrict__ bdt,
                 const float* __restrict__ A_log, const float* __restrict__ Dp)
{
    __shared__ __align__(16) float sD[32][164];   // dbc tile [t][0..160)
    int tid = threadIdx.x, lane = tid & 31, w = tid >> 5;
    int d = blockIdx.x * 8 + w;

    float wv  = Wdt[d * DTRANK + lane];           // Wdt[d][lane]
    float bd  = bdt[d];
    float A0  = -expf(A_log[d * DSTATE + lane]);
    float A1  = -expf(A_log[d * DSTATE + 32 + lane]);
    float Dpd = Dp[d];
    float h0 = 0.f, h1 = 0.f;

    const float* xT = g_xiT + d * SEQ;
    const float* zT = g_zsT + d * SEQ;
    float*       yT = g_yT  + d * SEQ;

    for (int t0 = 0; t0 < SEQ; t0 += 32) {
        __syncthreads();
        // stage 32x160 dbc rows: 1280 float4 / 256 threads = 5 each
        for (int i = tid; i < 32 * 40; i += 256) {
            int r = i / 40, q = (i % 40) * 4;
            *(float4*)&sD[r][q] = *(const float4*)&g_dbc[(t0 + r) * DBCCOLS + q];
        }
        __syncthreads();

        // fused delta for t = t0 + lane
        float accd = bd;
        #pragma unroll
        for (int r = 0; r < DTRANK; r++)
            accd = fmaf(sD[lane][r], __shfl_sync(0xffffffffu, wv, r), accd);
        float myD = softplusf(accd);

        float myX = xT[t0 + lane];
        float myZ = zT[t0 + lane];
        float yout = 0.f;

        #pragma unroll 4
        for (int i = 0; i < 32; i++) {
            float du = __shfl_sync(0xffffffffu, myD, i);
            float xv = __shfl_sync(0xffffffffu, myX, i);
            float dux = du * xv;
            h0 = __expf(du * A0) * h0 + dux * sD[i][32 + lane];
            h1 = __expf(du * A1) * h1 + dux * sD[i][64 + lane];
            float acc = h0 * sD[i][96 + lane] + h1 * sD[i][128 + lane];
            #pragma unroll
            for (int o = 16; o > 0; o >>= 1)
                acc += __shfl_xor_sync(0xffffffffu, acc, o);
            if (lane == i) yout = acc;
        }
        yT[t0 + lane] = (yout + Dpd * myX) * myZ;
    }
}

// ---------------- launcher ----------------
extern "C" void kernel_launch(void* const* d_in, const int* in_sizes, int n_in,
                              void* d_out, int out_size)
{
    const float* x      = (const float*)d_in[0];
    const float* ln_g   = (const float*)d_in[1];
    const float* ln_b   = (const float*)d_in[2];
    const float* Win    = (const float*)d_in[3];
    const float* conv_w = (const float*)d_in[4];
    const float* conv_b = (const float*)d_in[5];
    const float* Wx     = (const float*)d_in[6];
    const float* Wdt    = (const float*)d_in[7];
    const float* bdt    = (const float*)d_in[8];
    const float* A_log  = (const float*)d_in[9];
    const float* Dp     = (const float*)d_in[10];
    const float* Wout   = (const float*)d_in[11];
    float* out = (float*)d_out;

    float *p_xn, *p_xz, *p_xi, *p_dbcp, *p_yT;
    cudaGetSymbolAddress((void**)&p_xn,   g_xn);
    cudaGetSymbolAddress((void**)&p_xz,   g_xz);
    cudaGetSymbolAddress((void**)&p_xi,   g_xi);
    cudaGetSymbolAddress((void**)&p_dbcp, g_dbcp);
    cudaGetSymbolAddress((void**)&p_yT,   g_yT);

    // 1. LayerNorm
    ln_kernel<<<SEQ, 256>>>(x, ln_g, ln_b, p_xn);

    // 2. xz = xn @ Win^T   [2048 x 2048 x 512]  (128x128 tiles, 256 blocks)
    sgemm<128, 8, false, false><<<dim3(XZCOLS / 128, SEQ / 128), 256>>>(
        p_xn, DMODEL, Win, DMODEL, p_xz, XZCOLS, DMODEL, nullptr);

    // 3. conv + silu + transposes
    conv_kernel<<<dim3(SEQ / 32, DINNER / 32), 256>>>(conv_w, conv_b);

    // 4. dbc = xi @ Wx^T   [2048 x 160 x 1024]  split-K=4 + reduce
    gemm64_splitk<<<dim3((DBCCOLS + 63) / 64, SEQ / 64, NSPLIT), 256>>>(
        p_xi, DINNER, Wx, DINNER, p_dbcp, DBCCOLS,
        SEQ, DBCCOLS, DINNER / NSPLIT);
    reduce4_kernel<<<SEQ * DBCCOLS / 1024, 256>>>();

    // 5+6. selective scan with fused delta GEMV/softplus -> y^T
    scan_kernel<<<DINNER / 8, 256>>>(Wdt, bdt, A_log, Dp);

    // 7. out = y @ Wout^T + x   [2048 x 512 x 1024]  (128x64 tiles, A = y^T)
    sgemm<64, 4, true, true><<<dim3(DMODEL / 64, SEQ / 128), 256>>>(
        p_yT, SEQ, Wout, DINNER, out, DMODEL, DINNER, x);
}

// round 3
// speedup vs baseline: 1.1318x; 1.0202x over previous
#include <cuda_runtime.h>
#include <cuda_bf16.h>
#include <math.h>

// ---------------- problem constants ----------------
#define SEQ     2048
#define DMODEL  512
#define DINNER  1024
#define DSTATE  64
#define DTRANK  32
#define DCONV   4
#define XZCOLS  (2*DINNER)          // 2048
#define DBCCOLS (DTRANK + 2*DSTATE) // 160
#define NSPLIT  4

// ---------------- scratch (device globals; no allocation) ----------------
__device__ float g_xn  [SEQ*DMODEL];          // layernorm out        [t][d]
__device__ float g_xz  [SEQ*XZCOLS];          // xn @ Win^T           [t][e]
__device__ float g_xi  [SEQ*DINNER];          // conv+silu            [t][c]
__device__ float g_xiT [DINNER*SEQ];          // transposed           [c][t]
__device__ float g_zsT [DINNER*SEQ];          // silu(z) transposed   [c][t]
__device__ float g_dbcp[NSPLIT*SEQ*DBCCOLS];  // split-K partials
__device__ float g_dbc [SEQ*DBCCOLS];         // xi @ Wx^T            [t][r]
__device__ float g_yT  [DINNER*SEQ];          // scan output (y)      [c][t]

// ---------------- helpers ----------------
__device__ __forceinline__ float siluf(float x) { return x / (1.0f + __expf(-x)); }
__device__ __forceinline__ float softplusf(float x) {
    return (x > 15.0f) ? x : log1pf(__expf(x));
}

// ---------------- LayerNorm: one block per token ----------------
__global__ void ln_kernel(const float* __restrict__ x,
                          const float* __restrict__ g,
                          const float* __restrict__ b,
                          float* __restrict__ xn)
{
    int t   = blockIdx.x;
    int tid = threadIdx.x;             // 256 threads, 2 elems each
    const float* xr = x + t * DMODEL;
    float2 v = *(const float2*)&xr[tid * 2];
    float s = v.x + v.y;
    float q = v.x * v.x + v.y * v.y;
    #pragma unroll
    for (int o = 16; o > 0; o >>= 1) {
        s += __shfl_xor_sync(0xffffffffu, s, o);
        q += __shfl_xor_sync(0xffffffffu, q, o);
    }
    __shared__ float ss[8], qq[8];
    int lane = tid & 31, w = tid >> 5;
    if (lane == 0) { ss[w] = s; qq[w] = q; }
    __syncthreads();
    s = 0.f; q = 0.f;
    #pragma unroll
    for (int i = 0; i < 8; i++) { s += ss[i]; q += qq[i]; }
    float mu  = s * (1.0f / DMODEL);
    float var = q * (1.0f / DMODEL) - mu * mu;
    float r   = rsqrtf(var + 1e-5f);
    float2 gg = *(const float2*)&g[tid * 2];
    float2 bb = *(const float2*)&b[tid * 2];
    float2 o;
    o.x = (v.x - mu) * r * gg.x + bb.x;
    o.y = (v.y - mu) * r * gg.y + bb.y;
    *(float2*)&xn[t * DMODEL + tid * 2] = o;
}

// ---------------- unified SGEMM: BM=128, BK=8, TM=8, double buffered ----------------
// C[m][n] = sum_k A(m,k)*B[n][k]; B row-major [N][K].
// ATRANS=false: A row-major [M][K]. ATRANS=true: A stored [K][M].
// Conflict-free split fragments: rows {ty*4, 64+ty*4}, cols {tx*4, (64)+tx*4}.
// Split-K over blockIdx.z: K-slice [z*Ks, z*Ks+Ks), C offset z*M*ldc.
// NGUARD: guard B rows / C cols against N. RESID: C += resid.
template<int BN, int TN, bool ATRANS, bool RESID, bool NGUARD>
__global__ __launch_bounds__(256, 2)
void sgemm(const float* __restrict__ A, int lda,
           const float* __restrict__ B, int ldb,
           float* __restrict__ C, int ldc,
           int M, int N, int Ks,
           const float* __restrict__ resid)
{
    constexpr int BM = 128, BK = 8, TM = 8;
    __shared__ __align__(16) float As[2][BK][BM + 4];
    __shared__ __align__(16) float Bs[2][BK][BN + 4];

    const int tid = threadIdx.x;
    const int bm = blockIdx.y * BM;
    const int bn = blockIdx.x * BN;
    const int z  = blockIdx.z;
    const int kbeg = z * Ks, kend = kbeg + Ks;
    C += (size_t)z * M * ldc;

    const int tx = tid & 15;
    const int ty = tid >> 4;
    const int m0 = ty * 4;          // + 64 for second half
    const int n0 = tx * 4;          // + 64 for second half (TN==8)

    // A global->smem coords
    const int a_row = tid >> 1;            // !ATRANS: 0..127
    const int a_kq  = (tid & 1) << 2;      // 0 or 4
    const int at_k  = tid >> 5;            // ATRANS: 0..7
    const int at_m  = (tid & 31) << 2;     // 0..124

    // B global->smem coords
    const int b_row = (BN == 128) ? (tid >> 1) : (tid >> 2);
    const int b_kq  = (BN == 128) ? ((tid & 1) << 2) : ((tid & 3) << 1);

    float acc[TM][TN];
    #pragma unroll
    for (int i = 0; i < TM; i++)
        #pragma unroll
        for (int j = 0; j < TN; j++) acc[i][j] = 0.0f;

    float4 ra; float4 rb4; float2 rb2;

    auto loadA = [&](int k) {
        if (!ATRANS) ra = *(const float4*)&A[(bm + a_row) * lda + k + a_kq];
        else         ra = *(const float4*)&A[(k + at_k) * lda + bm + at_m];
    };
    auto loadB = [&](int k) {
        if (BN == 128) {
            if (NGUARD && bn + b_row >= N) rb4 = make_float4(0.f,0.f,0.f,0.f);
            else rb4 = *(const float4*)&B[(bn + b_row) * ldb + k + b_kq];
        } else {
            if (NGUARD && bn + b_row >= N) rb2 = make_float2(0.f,0.f);
            else rb2 = *(const float2*)&B[(bn + b_row) * ldb + k + b_kq];
        }
    };
    auto stA = [&](int buf) {
        if (!ATRANS) {
            As[buf][a_kq + 0][a_row] = ra.x; As[buf][a_kq + 1][a_row] = ra.y;
            As[buf][a_kq + 2][a_row] = ra.z; As[buf][a_kq + 3][a_row] = ra.w;
        } else {
            *(float4*)&As[buf][at_k][at_m] = ra;
        }
    };
    auto stB = [&](int buf) {
        if (BN == 128) {
            Bs[buf][b_kq + 0][b_row] = rb4.x; Bs[buf][b_kq + 1][b_row] = rb4.y;
            Bs[buf][b_kq + 2][b_row] = rb4.z; Bs[buf][b_kq + 3][b_row] = rb4.w;
        } else {
            Bs[buf][b_kq + 0][b_row] = rb2.x; Bs[buf][b_kq + 1][b_row] = rb2.y;
        }
    };

    loadA(kbeg); loadB(kbeg);
    stA(0); stB(0);
    __syncthreads();

    int cur = 0;
    for (int k0 = kbeg; k0 < kend; k0 += BK) {
        const int kn = k0 + BK;
        const bool has = kn < kend;
        if (has) { loadA(kn); loadB(kn); }
        #pragma unroll
        for (int kk = 0; kk < BK; kk++) {
            float4 a0 = *(const float4*)&As[cur][kk][m0];
            float4 a1 = *(const float4*)&As[cur][kk][m0 + 64];
            float rA[8] = {a0.x, a0.y, a0.z, a0.w, a1.x, a1.y, a1.z, a1.w};
            float rB[TN];
            {
                float4 b0 = *(const float4*)&Bs[cur][kk][n0];
                rB[0] = b0.x; rB[1] = b0.y; rB[2] = b0.z; rB[3] = b0.w;
                if (TN == 8) {
                    float4 b1 = *(const float4*)&Bs[cur][kk][n0 + 64];
                    rB[4] = b1.x; rB[5] = b1.y; rB[6] = b1.z; rB[7] = b1.w;
                }
            }
            #pragma unroll
            for (int i = 0; i < TM; i++)
                #pragma unroll
                for (int j = 0; j < TN; j++)
                    acc[i][j] = fmaf(rA[i], rB[j], acc[i][j]);
        }
        if (has) {
            cur ^= 1;
            stA(cur); stB(cur);
            __syncthreads();
        }
    }

    // ---- epilogue: rows {bm+m0+i, bm+64+m0+i}, col quads {bn+n0, bn+64+n0} ----
    #pragma unroll
    for (int half = 0; half < 2; half++) {
        #pragma unroll
        for (int i = 0; i < 4; i++) {
            int m = bm + half * 64 + m0 + i;
            int ai = half * 4 + i;
            #pragma unroll
            for (int jq = 0; jq < TN / 4; jq++) {
                int n = bn + jq * 64 + n0;
                if (NGUARD && n >= N) continue;
                float4 v = make_float4(acc[ai][jq*4+0], acc[ai][jq*4+1],
                                       acc[ai][jq*4+2], acc[ai][jq*4+3]);
                if (RESID) {
                    float4 r = *(const float4*)&resid[m * ldc + n];
                    v.x += r.x; v.y += r.y; v.z += r.z; v.w += r.w;
                }
                *(float4*)&C[m * ldc + n] = v;
            }
        }
    }
}

// deterministic reduce of the 4 split-K partials (float4 per thread)
__global__ void reduce4_kernel()
{
    int i = (blockIdx.x * 256 + threadIdx.x) * 4;   // float index
    const int TOT = SEQ * DBCCOLS;
    float4 a = *(const float4*)&g_dbcp[0 * TOT + i];
    float4 b = *(const float4*)&g_dbcp[1 * TOT + i];
    float4 c = *(const float4*)&g_dbcp[2 * TOT + i];
    float4 d = *(const float4*)&g_dbcp[3 * TOT + i];
    float4 o;
    o.x = (a.x + b.x) + (c.x + d.x);
    o.y = (a.y + b.y) + (c.y + d.y);
    o.z = (a.z + b.z) + (c.z + d.z);
    o.w = (a.w + b.w) + (c.w + d.w);
    *(float4*)&g_dbc[i] = o;
}

// ---------------- depthwise conv (width 4, causal) + silu + transposes ----------------
__global__ __launch_bounds__(256)
void conv_kernel(const float* __restrict__ cw, const float* __restrict__ cb)
{
    __shared__ float sxz[35][33];
    __shared__ float sxi[32][33];
    __shared__ float szs[32][33];
    int t0 = blockIdx.x * 32, c0 = blockIdx.y * 32;
    int tid = threadIdx.x;

    for (int i = tid; i < 35 * 32; i += 256) {
        int r = i >> 5, c = i & 31;
        int gt = t0 + r - 3;
        sxz[r][c] = (gt >= 0) ? g_xz[gt * XZCOLS + c0 + c] : 0.0f;
    }
    for (int i = tid; i < 32 * 32; i += 256) {
        int r = i >> 5, c = i & 31;
        float z = g_xz[(t0 + r) * XZCOLS + DINNER + c0 + c];
        szs[r][c] = siluf(z);
    }
    __syncthreads();

    int cl = tid & 31, tq = tid >> 5;
    float4 w = *(const float4*)&cw[(c0 + cl) * 4];
    float bb = cb[c0 + cl];
    #pragma unroll
    for (int s = 0; s < 4; s++) {
        int tl = tq + s * 8;
        float v = sxz[tl + 0][cl] * w.x + sxz[tl + 1][cl] * w.y +
                  sxz[tl + 2][cl] * w.z + sxz[tl + 3][cl] * w.w + bb;
        v = siluf(v);
        g_xi[(t0 + tl) * DINNER + c0 + cl] = v;
        sxi[tl][cl] = v;
    }
    __syncthreads();

    int tl2 = tid & 31, cq = tid >> 5;
    #pragma unroll
    for (int s = 0; s < 4; s++) {
        int cl2 = cq + s * 8;
        g_xiT[(c0 + cl2) * SEQ + t0 + tl2] = sxi[tl2][cl2];
        g_zsT[(c0 + cl2) * SEQ + t0 + tl2] = szs[tl2][cl2];
    }
}

// ---------------- selective scan with fused delta GEMV + softplus ----------------
__global__ __launch_bounds__(256)
void scan_kernel(const float* __restrict__ Wdt, const float* __restrict__ bdt,
                 const float* __restrict__ A_log, const float* __restrict__ Dp)
{
    __shared__ __align__(16) float sD[32][164];   // dbc tile [t][0..160)
    int tid = threadIdx.x, lane = tid & 31, w = tid >> 5;
    int d = blockIdx.x * 8 + w;

    float wv  = Wdt[d * DTRANK + lane];           // Wdt[d][lane]
    float bd  = bdt[d];
    float A0  = -expf(A_log[d * DSTATE + lane]);
    float A1  = -expf(A_log[d * DSTATE + 32 + lane]);
    float Dpd = Dp[d];
    float h0 = 0.f, h1 = 0.f;

    const float* xT = g_xiT + d * SEQ;
    const float* zT = g_zsT + d * SEQ;
    float*       yT = g_yT  + d * SEQ;

    for (int t0 = 0; t0 < SEQ; t0 += 32) {
        __syncthreads();
        for (int i = tid; i < 32 * 40; i += 256) {
            int r = i / 40, q = (i % 40) * 4;
            *(float4*)&sD[r][q] = *(const float4*)&g_dbc[(t0 + r) * DBCCOLS + q];
        }
        __syncthreads();

        // fused delta for t = t0 + lane
        float accd = bd;
        #pragma unroll
        for (int r = 0; r < DTRANK; r++)
            accd = fmaf(sD[lane][r], __shfl_sync(0xffffffffu, wv, r), accd);
        float myD = softplusf(accd);

        float myX = xT[t0 + lane];
        float myZ = zT[t0 + lane];
        float yout = 0.f;

        #pragma unroll 4
        for (int i = 0; i < 32; i++) {
            float du = __shfl_sync(0xffffffffu, myD, i);
            float xv = __shfl_sync(0xffffffffu, myX, i);
            float dux = du * xv;
            h0 = __expf(du * A0) * h0 + dux * sD[i][32 + lane];
            h1 = __expf(du * A1) * h1 + dux * sD[i][64 + lane];
            float acc = h0 * sD[i][96 + lane] + h1 * sD[i][128 + lane];
            #pragma unroll
            for (int o = 16; o > 0; o >>= 1)
                acc += __shfl_xor_sync(0xffffffffu, acc, o);
            if (lane == i) yout = acc;
        }
        yT[t0 + lane] = (yout + Dpd * myX) * myZ;
    }
}

// ---------------- launcher ----------------
extern "C" void kernel_launch(void* const* d_in, const int* in_sizes, int n_in,
                              void* d_out, int out_size)
{
    const float* x      = (const float*)d_in[0];
    const float* ln_g   = (const float*)d_in[1];
    const float* ln_b   = (const float*)d_in[2];
    const float* Win    = (const float*)d_in[3];
    const float* conv_w = (const float*)d_in[4];
    const float* conv_b = (const float*)d_in[5];
    const float* Wx     = (const float*)d_in[6];
    const float* Wdt    = (const float*)d_in[7];
    const float* bdt    = (const float*)d_in[8];
    const float* A_log  = (const float*)d_in[9];
    const float* Dp     = (const float*)d_in[10];
    const float* Wout   = (const float*)d_in[11];
    float* out = (float*)d_out;

    float *p_xn, *p_xz, *p_xi, *p_dbcp, *p_yT;
    cudaGetSymbolAddress((void**)&p_xn,   g_xn);
    cudaGetSymbolAddress((void**)&p_xz,   g_xz);
    cudaGetSymbolAddress((void**)&p_xi,   g_xi);
    cudaGetSymbolAddress((void**)&p_dbcp, g_dbcp);
    cudaGetSymbolAddress((void**)&p_yT,   g_yT);

    // 1. LayerNorm
    ln_kernel<<<SEQ, 256>>>(x, ln_g, ln_b, p_xn);

    // 2. xz = xn @ Win^T   [2048 x 2048 x 512]  (128x128 tiles, 256 blocks)
    sgemm<128, 8, false, false, false><<<dim3(XZCOLS / 128, SEQ / 128, 1), 256>>>(
        p_xn, DMODEL, Win, DMODEL, p_xz, XZCOLS, SEQ, XZCOLS, DMODEL, nullptr);

    // 3. conv + silu + transposes
    conv_kernel<<<dim3(SEQ / 32, DINNER / 32), 256>>>(conv_w, conv_b);

    // 4. dbc = xi @ Wx^T   [2048 x 160 x 1024]  128x64 tiles, split-K=4 + reduce
    sgemm<64, 4, false, false, true><<<dim3(3, SEQ / 128, NSPLIT), 256>>>(
        p_xi, DINNER, Wx, DINNER, p_dbcp, DBCCOLS, SEQ, DBCCOLS,
        DINNER / NSPLIT, nullptr);
    reduce4_kernel<<<SEQ * DBCCOLS / 1024, 256>>>();

    // 5+6. selective scan with fused delta GEMV/softplus -> y^T
    scan_kernel<<<DINNER / 8, 256>>>(Wdt, bdt, A_log, Dp);

    // 7. out = y @ Wout^T + x   [2048 x 512 x 1024]  (128x64 tiles, A = y^T)
    sgemm<64, 4, true, true, false><<<dim3(DMODEL / 64, SEQ / 128, 1), 256>>>(
        p_yT, SEQ, Wout, DINNER, out, DMODEL, SEQ, DMODEL, DINNER, x);
}

// round 4
// speedup vs baseline: 1.4095x; 1.2453x over previous
#include <cuda_runtime.h>
#include <cuda_bf16.h>
#include <math.h>

// ---------------- problem constants ----------------
#define SEQ     2048
#define DMODEL  512
#define DINNER  1024
#define DSTATE  64
#define DTRANK  32
#define DCONV   4
#define XZCOLS  (2*DINNER)          // 2048
#define DBCCOLS (DTRANK + 2*DSTATE) // 160
#define NSPLIT  4

// ---------------- scratch (device globals; no allocation) ----------------
__device__ float g_xn  [SEQ*DMODEL];
__device__ float g_xz  [SEQ*XZCOLS];
__device__ float g_xi  [SEQ*DINNER];
__device__ float g_xiT [DINNER*SEQ];
__device__ float g_zsT [DINNER*SEQ];
__device__ float g_dbcp[NSPLIT*SEQ*DBCCOLS];
__device__ float g_dbc [SEQ*DBCCOLS];
__device__ float g_yT  [DINNER*SEQ];

// ---------------- helpers ----------------
__device__ __forceinline__ float siluf(float x) { return x / (1.0f + __expf(-x)); }
__device__ __forceinline__ float softplusf(float x) {
    return (x > 15.0f) ? x : log1pf(__expf(x));
}

// packed fp32x2 FMA (Blackwell FFMA2, PTX-only)
__device__ __forceinline__ unsigned long long fma2(unsigned long long a,
                                                   unsigned long long b,
                                                   unsigned long long c) {
    unsigned long long d;
    asm("fma.rn.f32x2 %0, %1, %2, %3;" : "=l"(d) : "l"(a), "l"(b), "l"(c));
    return d;
}
__device__ __forceinline__ unsigned long long pack2(float x, float y) {
    unsigned long long d;
    asm("mov.b64 %0, {%1, %2};" : "=l"(d) : "f"(x), "f"(y));
    return d;
}
__device__ __forceinline__ float2 unpack2(unsigned long long v) {
    float2 f;
    asm("mov.b64 {%0, %1}, %2;" : "=f"(f.x), "=f"(f.y) : "l"(v));
    return f;
}

// ---------------- LayerNorm: one block per token ----------------
__global__ void ln_kernel(const float* __restrict__ x,
                          const float* __restrict__ g,
                          const float* __restrict__ b,
                          float* __restrict__ xn)
{
    int t   = blockIdx.x;
    int tid = threadIdx.x;
    const float* xr = x + t * DMODEL;
    float2 v = *(const float2*)&xr[tid * 2];
    float s = v.x + v.y;
    float q = v.x * v.x + v.y * v.y;
    #pragma unroll
    for (int o = 16; o > 0; o >>= 1) {
        s += __shfl_xor_sync(0xffffffffu, s, o);
        q += __shfl_xor_sync(0xffffffffu, q, o);
    }
    __shared__ float ss[8], qq[8];
    int lane = tid & 31, w = tid >> 5;
    if (lane == 0) { ss[w] = s; qq[w] = q; }
    __syncthreads();
    s = 0.f; q = 0.f;
    #pragma unroll
    for (int i = 0; i < 8; i++) { s += ss[i]; q += qq[i]; }
    float mu  = s * (1.0f / DMODEL);
    float var = q * (1.0f / DMODEL) - mu * mu;
    float r   = rsqrtf(var + 1e-5f);
    float2 gg = *(const float2*)&g[tid * 2];
    float2 bb = *(const float2*)&b[tid * 2];
    float2 o;
    o.x = (v.x - mu) * r * gg.x + bb.x;
    o.y = (v.y - mu) * r * gg.y + bb.y;
    *(float2*)&xn[t * DMODEL + tid * 2] = o;
}

// ---------------- unified SGEMM, FFMA2 inner product ----------------
// C[m][n] = sum_k A(m,k)*B[n][k]; B row-major [N][K].
template<int BN, int TN, bool ATRANS, bool RESID, bool NGUARD>
__global__ __launch_bounds__(256, 2)
void sgemm(const float* __restrict__ A, int lda,
           const float* __restrict__ B, int ldb,
           float* __restrict__ C, int ldc,
           int M, int N, int Ks,
           const float* __restrict__ resid)
{
    constexpr int BM = 128, BK = 8, TM = 8;
    __shared__ __align__(16) float As[2][BK][BM + 4];
    __shared__ __align__(16) float Bs[2][BK][BN + 4];

    const int tid = threadIdx.x;
    const int bm = blockIdx.y * BM;
    const int bn = blockIdx.x * BN;
    const int z  = blockIdx.z;
    const int kbeg = z * Ks, kend = kbeg + Ks;
    C += (size_t)z * M * ldc;

    const int tx = tid & 15;
    const int ty = tid >> 4;
    const int m0 = ty * 4;
    const int n0 = tx * 4;

    const int a_row = tid >> 1;
    const int a_kq  = (tid & 1) << 2;
    const int at_k  = tid >> 5;
    const int at_m  = (tid & 31) << 2;

    const int b_row = (BN == 128) ? (tid >> 1) : (tid >> 2);
    const int b_kq  = (BN == 128) ? ((tid & 1) << 2) : ((tid & 3) << 1);

    unsigned long long acc2[TM][TN / 2];
    #pragma unroll
    for (int i = 0; i < TM; i++)
        #pragma unroll
        for (int j = 0; j < TN / 2; j++) acc2[i][j] = 0ull;

    float4 ra; float4 rb4; float2 rb2;

    auto loadA = [&](int k) {
        if (!ATRANS) ra = *(const float4*)&A[(bm + a_row) * lda + k + a_kq];
        else         ra = *(const float4*)&A[(k + at_k) * lda + bm + at_m];
    };
    auto loadB = [&](int k) {
        if (BN == 128) {
            if (NGUARD && bn + b_row >= N) rb4 = make_float4(0.f,0.f,0.f,0.f);
            else rb4 = *(const float4*)&B[(bn + b_row) * ldb + k + b_kq];
        } else {
            if (NGUARD && bn + b_row >= N) rb2 = make_float2(0.f,0.f);
            else rb2 = *(const float2*)&B[(bn + b_row) * ldb + k + b_kq];
        }
    };
    auto stA = [&](int buf) {
        if (!ATRANS) {
            As[buf][a_kq + 0][a_row] = ra.x; As[buf][a_kq + 1][a_row] = ra.y;
            As[buf][a_kq + 2][a_row] = ra.z; As[buf][a_kq + 3][a_row] = ra.w;
        } else {
            *(float4*)&As[buf][at_k][at_m] = ra;
        }
    };
    auto stB = [&](int buf) {
        if (BN == 128) {
            Bs[buf][b_kq + 0][b_row] = rb4.x; Bs[buf][b_kq + 1][b_row] = rb4.y;
            Bs[buf][b_kq + 2][b_row] = rb4.z; Bs[buf][b_kq + 3][b_row] = rb4.w;
        } else {
            Bs[buf][b_kq + 0][b_row] = rb2.x; Bs[buf][b_kq + 1][b_row] = rb2.y;
        }
    };

    loadA(kbeg); loadB(kbeg);
    stA(0); stB(0);
    __syncthreads();

    int cur = 0;
    for (int k0 = kbeg; k0 < kend; k0 += BK) {
        const int kn = k0 + BK;
        const bool has = kn < kend;
        if (has) { loadA(kn); loadB(kn); }
        #pragma unroll
        for (int kk = 0; kk < BK; kk++) {
            float4 a0 = *(const float4*)&As[cur][kk][m0];
            float4 a1 = *(const float4*)&As[cur][kk][m0 + 64];
            unsigned long long aa[TM];
            aa[0] = pack2(a0.x, a0.x); aa[1] = pack2(a0.y, a0.y);
            aa[2] = pack2(a0.z, a0.z); aa[3] = pack2(a0.w, a0.w);
            aa[4] = pack2(a1.x, a1.x); aa[5] = pack2(a1.y, a1.y);
            aa[6] = pack2(a1.z, a1.z); aa[7] = pack2(a1.w, a1.w);
            unsigned long long bb[TN / 2];
            {
                ulonglong2 b0 = *(const ulonglong2*)&Bs[cur][kk][n0];
                bb[0] = b0.x; bb[1] = b0.y;
                if (TN == 8) {
                    ulonglong2 b1 = *(const ulonglong2*)&Bs[cur][kk][n0 + 64];
                    bb[2] = b1.x; bb[3] = b1.y;
                }
            }
            #pragma unroll
            for (int i = 0; i < TM; i++)
                #pragma unroll
                for (int j = 0; j < TN / 2; j++)
                    acc2[i][j] = fma2(aa[i], bb[j], acc2[i][j]);
        }
        if (has) {
            cur ^= 1;
            stA(cur); stB(cur);
            __syncthreads();
        }
    }

    // ---- epilogue ----
    #pragma unroll
    for (int half = 0; half < 2; half++) {
        #pragma unroll
        for (int i = 0; i < 4; i++) {
            int m = bm + half * 64 + m0 + i;
            int ai = half * 4 + i;
            #pragma unroll
            for (int jq = 0; jq < TN / 4; jq++) {
                int n = bn + jq * 64 + n0;
                if (NGUARD && n >= N) continue;
                float2 v0 = unpack2(acc2[ai][jq * 2 + 0]);
                float2 v1 = unpack2(acc2[ai][jq * 2 + 1]);
                float4 v = make_float4(v0.x, v0.y, v1.x, v1.y);
                if (RESID) {
                    float4 r = *(const float4*)&resid[m * ldc + n];
                    v.x += r.x; v.y += r.y; v.z += r.z; v.w += r.w;
                }
                *(float4*)&C[m * ldc + n] = v;
            }
        }
    }
}

// deterministic reduce of the 4 split-K partials
__global__ void reduce4_kernel()
{
    int i = (blockIdx.x * 256 + threadIdx.x) * 4;
    const int TOT = SEQ * DBCCOLS;
    float4 a = *(const float4*)&g_dbcp[0 * TOT + i];
    float4 b = *(const float4*)&g_dbcp[1 * TOT + i];
    float4 c = *(const float4*)&g_dbcp[2 * TOT + i];
    float4 d = *(const float4*)&g_dbcp[3 * TOT + i];
    float4 o;
    o.x = (a.x + b.x) + (c.x + d.x);
    o.y = (a.y + b.y) + (c.y + d.y);
    o.z = (a.z + b.z) + (c.z + d.z);
    o.w = (a.w + b.w) + (c.w + d.w);
    *(float4*)&g_dbc[i] = o;
}

// ---------------- depthwise conv + silu + transposes ----------------
__global__ __launch_bounds__(256)
void conv_kernel(const float* __restrict__ cw, const float* __restrict__ cb)
{
    __shared__ float sxz[35][33];
    __shared__ float sxi[32][33];
    __shared__ float szs[32][33];
    int t0 = blockIdx.x * 32, c0 = blockIdx.y * 32;
    int tid = threadIdx.x;

    for (int i = tid; i < 35 * 32; i += 256) {
        int r = i >> 5, c = i & 31;
        int gt = t0 + r - 3;
        sxz[r][c] = (gt >= 0) ? g_xz[gt * XZCOLS + c0 + c] : 0.0f;
    }
    for (int i = tid; i < 32 * 32; i += 256) {
        int r = i >> 5, c = i & 31;
        float z = g_xz[(t0 + r) * XZCOLS + DINNER + c0 + c];
        szs[r][c] = siluf(z);
    }
    __syncthreads();

    int cl = tid & 31, tq = tid >> 5;
    float4 w = *(const float4*)&cw[(c0 + cl) * 4];
    float bb = cb[c0 + cl];
    #pragma unroll
    for (int s = 0; s < 4; s++) {
        int tl = tq + s * 8;
        float v = sxz[tl + 0][cl] * w.x + sxz[tl + 1][cl] * w.y +
                  sxz[tl + 2][cl] * w.z + sxz[tl + 3][cl] * w.w + bb;
        v = siluf(v);
        g_xi[(t0 + tl) * DINNER + c0 + cl] = v;
        sxi[tl][cl] = v;
    }
    __syncthreads();

    int tl2 = tid & 31, cq = tid >> 5;
    #pragma unroll
    for (int s = 0; s < 4; s++) {
        int cl2 = cq + s * 8;
        g_xiT[(c0 + cl2) * SEQ + t0 + tl2] = sxi[tl2][cl2];
        g_zsT[(c0 + cl2) * SEQ + t0 + tl2] = szs[tl2][cl2];
    }
}

// ---------------- selective scan: deferred butterfly reduction ----------------
// One warp per channel d. delta fused (GEMV+softplus). Per 32-t tile the lane
// accumulates p[i] (partial y for timestep i) in registers; a 31-shfl
// recursive-halving exchange then lands y[t0+lane] on lane t. The second exp
// is replaced by e0 * exp(du*(A1-A0)) when A1-A0 is lane-uniform (runtime check).
__global__ __launch_bounds__(256)
void scan_kernel(const float* __restrict__ Wdt, const float* __restrict__ bdt,
                 const float* __restrict__ A_log, const float* __restrict__ Dp)
{
    __shared__ __align__(16) float sD[32][164];   // dbc tile [t][0..160)
    const unsigned FULL = 0xffffffffu;
    int tid = threadIdx.x, lane = tid & 31, w = tid >> 5;
    int d = blockIdx.x * 8 + w;

    float wv  = Wdt[d * DTRANK + lane];
    float bd  = bdt[d];
    float A0  = -expf(A_log[d * DSTATE + lane]);
    float A1  = -expf(A_log[d * DSTATE + 32 + lane]);
    float d32 = A1 - A0;
    bool uni  = __all_sync(FULL, __shfl_sync(FULL, d32, 0) == d32);
    float Dpd = Dp[d];
    float h0 = 0.f, h1 = 0.f;

    const float* xT = g_xiT + d * SEQ;
    const float* zT = g_zsT + d * SEQ;
    float*       yT = g_yT  + d * SEQ;

    for (int t0 = 0; t0 < SEQ; t0 += 32) {
        __syncthreads();
        for (int i = tid; i < 32 * 40; i += 256) {
            int r = i / 40, q = (i % 40) * 4;
            *(float4*)&sD[r][q] = *(const float4*)&g_dbc[(t0 + r) * DBCCOLS + q];
        }
        __syncthreads();

        // fused delta for t = t0 + lane
        float accd = bd;
        #pragma unroll
        for (int r = 0; r < DTRANK; r++)
            accd = fmaf(sD[lane][r], __shfl_sync(FULL, wv, r), accd);
        float myD = softplusf(accd);

        float myX   = xT[t0 + lane];
        float myZ   = zT[t0 + lane];
        float myDux = myD * myX;
        float myE32 = __expf(myD * d32);   // exp(du*(A1-A0)) for this lane's t

        float p[32];
        #pragma unroll
        for (int i = 0; i < 32; i++) {
            float du  = __shfl_sync(FULL, myD,   i);
            float dux = __shfl_sync(FULL, myDux, i);
            float e0  = __expf(du * A0);
            float e1;
            if (uni) e1 = e0 * __shfl_sync(FULL, myE32, i);
            else     e1 = __expf(du * A1);
            h0 = fmaf(e0, h0, dux * sD[i][32 + lane]);
            h1 = fmaf(e1, h1, dux * sD[i][64 + lane]);
            p[i] = fmaf(h0, sD[i][96 + lane], h1 * sD[i][128 + lane]);
        }

        // butterfly transpose-reduce: y[i] = sum_lanes p[i], result on lane i
        #pragma unroll
        for (int o = 16; o >= 1; o >>= 1) {
            bool hi = (lane & o) != 0;
            #pragma unroll
            for (int jj = 0; jj < o; jj++) {
                float keep = hi ? p[o + jj] : p[jj];
                float send = hi ? p[jj] : p[o + jj];
                p[jj] = keep + __shfl_xor_sync(FULL, send, o);
            }
        }

        yT[t0 + lane] = (p[0] + Dpd * myX) * myZ;
    }
}

// ---------------- launcher ----------------
extern "C" void kernel_launch(void* const* d_in, const int* in_sizes, int n_in,
                              void* d_out, int out_size)
{
    const float* x      = (const float*)d_in[0];
    const float* ln_g   = (const float*)d_in[1];
    const float* ln_b   = (const float*)d_in[2];
    const float* Win    = (const float*)d_in[3];
    const float* conv_w = (const float*)d_in[4];
    const float* conv_b = (const float*)d_in[5];
    const float* Wx     = (const float*)d_in[6];
    const float* Wdt    = (const float*)d_in[7];
    const float* bdt    = (const float*)d_in[8];
    const float* A_log  = (const float*)d_in[9];
    const float* Dp     = (const float*)d_in[10];
    const float* Wout   = (const float*)d_in[11];
    float* out = (float*)d_out;

    float *p_xn, *p_xz, *p_xi, *p_dbcp, *p_yT;
    cudaGetSymbolAddress((void**)&p_xn,   g_xn);
    cudaGetSymbolAddress((void**)&p_xz,   g_xz);
    cudaGetSymbolAddress((void**)&p_xi,   g_xi);
    cudaGetSymbolAddress((void**)&p_dbcp, g_dbcp);
    cudaGetSymbolAddress((void**)&p_yT,   g_yT);

    // 1. LayerNorm
    ln_kernel<<<SEQ, 256>>>(x, ln_g, ln_b, p_xn);

    // 2. xz = xn @ Win^T   [2048 x 2048 x 512]
    sgemm<128, 8, false, false, false><<<dim3(XZCOLS / 128, SEQ / 128, 1), 256>>>(
        p_xn, DMODEL, Win, DMODEL, p_xz, XZCOLS, SEQ, XZCOLS, DMODEL, nullptr);

    // 3. conv + silu + transposes
    conv_kernel<<<dim3(SEQ / 32, DINNER / 32), 256>>>(conv_w, conv_b);

    // 4. dbc = xi @ Wx^T   [2048 x 160 x 1024]  split-K=4 + reduce
    sgemm<64, 4, false, false, true><<<dim3(3, SEQ / 128, NSPLIT), 256>>>(
        p_xi, DINNER, Wx, DINNER, p_dbcp, DBCCOLS, SEQ, DBCCOLS,
        DINNER / NSPLIT, nullptr);
    reduce4_kernel<<<SEQ * DBCCOLS / 1024, 256>>>();

    // 5+6. selective scan (fused delta) -> y^T
    scan_kernel<<<DINNER / 8, 256>>>(Wdt, bdt, A_log, Dp);

    // 7. out = y @ Wout^T + x   [2048 x 512 x 1024]
    sgemm<64, 4, true, true, false><<<dim3(DMODEL / 64, SEQ / 128, 1), 256>>>(
        p_yT, SEQ, Wout, DINNER, out, DMODEL, SEQ, DMODEL, DINNER, x);
}

// round 6
// speedup vs baseline: 1.6180x; 1.1479x over previous
#include <cuda_runtime.h>
#include <cuda_bf16.h>
#include <math.h>
#include <stdint.h>

// ---------------- problem constants ----------------
#define SEQ     2048
#define DMODEL  512
#define DINNER  1024
#define DSTATE  64
#define DTRANK  32
#define DCONV   4
#define XZCOLS  (2*DINNER)          // 2048
#define DBCCOLS (DTRANK + 2*DSTATE) // 160
#define NSPLIT  4

// ---------------- scratch (device globals; no allocation) ----------------
__device__ float g_xn  [SEQ*DMODEL];
__device__ float g_xz  [SEQ*XZCOLS];
__device__ float g_xi  [SEQ*DINNER];
__device__ float g_xiT [DINNER*SEQ];
__device__ float g_zsT [DINNER*SEQ];
__device__ float g_dbcp[NSPLIT*SEQ*DBCCOLS];
__device__ float g_dbc [SEQ*DBCCOLS];
__device__ float g_y   [SEQ*DINNER];          // scan output, row-major [t][c]

// ---------------- helpers ----------------
__device__ __forceinline__ float siluf(float x) { return x / (1.0f + __expf(-x)); }
__device__ __forceinline__ float softplusf(float x) {
    return (x > 15.0f) ? x : log1pf(__expf(x));
}

// packed fp32x2 FMA (Blackwell FFMA2, PTX-only)
__device__ __forceinline__ unsigned long long fma2(unsigned long long a,
                                                   unsigned long long b,
                                                   unsigned long long c) {
    unsigned long long d;
    asm("fma.rn.f32x2 %0, %1, %2, %3;" : "=l"(d) : "l"(a), "l"(b), "l"(c));
    return d;
}
__device__ __forceinline__ unsigned long long pack2(float x, float y) {
    unsigned long long d;
    asm("mov.b64 %0, {%1, %2};" : "=l"(d) : "f"(x), "f"(y));
    return d;
}
__device__ __forceinline__ float2 unpack2(unsigned long long v) {
    float2 f;
    asm("mov.b64 {%0, %1}, %2;" : "=f"(f.x), "=f"(f.y) : "l"(v));
    return f;
}

__device__ __forceinline__ uint32_t smem_u32(const void* p) {
    uint32_t a;
    asm("{ .reg .u64 t; cvta.to.shared.u64 t, %1; cvt.u32.u64 %0, t; }"
        : "=r"(a) : "l"(p));
    return a;
}
__device__ __forceinline__ void ldsm4(uint32_t& r0, uint32_t& r1,
                                      uint32_t& r2, uint32_t& r3, uint32_t addr) {
    asm volatile("ldmatrix.sync.aligned.m8n8.x4.shared.b16 {%0,%1,%2,%3}, [%4];"
                 : "=r"(r0), "=r"(r1), "=r"(r2), "=r"(r3) : "r"(addr));
}
__device__ __forceinline__ void mma_bf16(float* c, uint32_t a0, uint32_t a1,
                                         uint32_t a2, uint32_t a3,
                                         uint32_t b0, uint32_t b1) {
    asm volatile(
        "mma.sync.aligned.m16n8k16.row.col.f32.bf16.bf16.f32 "
        "{%0,%1,%2,%3}, {%4,%5,%6,%7}, {%8,%9}, {%0,%1,%2,%3};"
        : "+f"(c[0]), "+f"(c[1]), "+f"(c[2]), "+f"(c[3])
        : "r"(a0), "r"(a1), "r"(a2), "r"(a3), "r"(b0), "r"(b1));
}

// ---------------- LayerNorm: one block per token ----------------
__global__ void ln_kernel(const float* __restrict__ x,
                          const float* __restrict__ g,
                          const float* __restrict__ b,
                          float* __restrict__ xn)
{
    int t   = blockIdx.x;
    int tid = threadIdx.x;
    const float* xr = x + t * DMODEL;
    float2 v = *(const float2*)&xr[tid * 2];
    float s = v.x + v.y;
    float q = v.x * v.x + v.y * v.y;
    #pragma unroll
    for (int o = 16; o > 0; o >>= 1) {
        s += __shfl_xor_sync(0xffffffffu, s, o);
        q += __shfl_xor_sync(0xffffffffu, q, o);
    }
    __shared__ float ss[8], qq[8];
    int lane = tid & 31, w = tid >> 5;
    if (lane == 0) { ss[w] = s; qq[w] = q; }
    __syncthreads();
    s = 0.f; q = 0.f;
    #pragma unroll
    for (int i = 0; i < 8; i++) { s += ss[i]; q += qq[i]; }
    float mu  = s * (1.0f / DMODEL);
    float var = q * (1.0f / DMODEL) - mu * mu;
    float r   = rsqrtf(var + 1e-5f);
    float2 gg = *(const float2*)&g[tid * 2];
    float2 bb = *(const float2*)&b[tid * 2];
    float2 o;
    o.x = (v.x - mu) * r * gg.x + bb.x;
    o.y = (v.y - mu) * r * gg.y + bb.y;
    *(float2*)&xn[t * DMODEL + tid * 2] = o;
}

// ---------------- split-bf16 HMMA GEMM (mma.sync, baseline PTX) ----------------
// C[m][n] = sum_k A[m][k]*B[n][k]; A row-major [M][K], B row-major [N][K].
// D = Ahi*Bhi + Ahi*Blo + Alo*Bhi, fp32 accum.
// BK = 32, smem rows padded to 40 bf16 (80 B) -> conflict-free ldmatrix.
// 8 warps in 2(m) x 4(n) grid; warp tile (BM/2) x (BN/4).
template<int BM, int BN, bool RESID>
__global__ __launch_bounds__(256)
void mma_gemm(const float* __restrict__ A, int lda,
              const float* __restrict__ B, int ldb,
              float* __restrict__ C, int ldc,
              int K, const float* __restrict__ resid)
{
    constexpr int S = 40;                       // padded row stride (bf16)
    constexpr int MT = (BM / 2) / 16;           // m16 tiles per warp
    constexpr int NT = (BN / 4) / 8;            // n8 tiles per warp
    constexpr int AITER = BM / 32;              // float4 loads per thread (A)
    constexpr int BITER = BN / 32;
    constexpr int PERBUF = 2 * BM * S + 2 * BN * S;   // bf16 units per buffer

    extern __shared__ __align__(16) __nv_bfloat16 sm[];
    const uint32_t sb = smem_u32(sm);

    const int tid = threadIdx.x, lane = tid & 31, wid = tid >> 5;
    const int bm = blockIdx.y * BM, bn = blockIdx.x * BN;
    const int wm0 = (wid & 1) * (BM / 2);
    const int wn0 = (wid >> 1) * (BN / 4);

    // ldmatrix lane coords
    const int lA_r = lane & 15;
    const int lA_c = (lane >> 4) << 3;
    const int lB_r = (lane & 7) + ((lane >> 4) << 3);
    const int lB_c = ((lane >> 3) & 1) << 3;

    float acc[MT][NT][4];
    #pragma unroll
    for (int i = 0; i < MT; i++)
        #pragma unroll
        for (int j = 0; j < NT; j++)
            #pragma unroll
            for (int q = 0; q < 4; q++) acc[i][j][q] = 0.0f;

    float4 va[AITER], vb[BITER];

    auto loadG = [&](int k0) {
        #pragma unroll
        for (int i = 0; i < AITER; i++) {
            int idx = tid + i * 256;
            int r = idx >> 3, cq = (idx & 7) << 2;
            va[i] = *(const float4*)&A[(size_t)(bm + r) * lda + k0 + cq];
        }
        #pragma unroll
        for (int i = 0; i < BITER; i++) {
            int idx = tid + i * 256;
            int r = idx >> 3, cq = (idx & 7) << 2;
            vb[i] = *(const float4*)&B[(size_t)(bn + r) * ldb + k0 + cq];
        }
    };
    auto storeS = [&](int buf) {
        const int oAhi = buf * PERBUF;
        const int oAlo = oAhi + BM * S;
        const int oBhi = oAhi + 2 * BM * S;
        const int oBlo = oBhi + BN * S;
        #pragma unroll
        for (int i = 0; i < AITER; i++) {
            int idx = tid + i * 256;
            int r = idx >> 3, cq = (idx & 7) << 2;
            float4 v = va[i];
            __nv_bfloat162 h0 = __floats2bfloat162_rn(v.x, v.y);
            __nv_bfloat162 h1 = __floats2bfloat162_rn(v.z, v.w);
            __nv_bfloat162 l0 = __floats2bfloat162_rn(
                v.x - __bfloat162float(h0.x), v.y - __bfloat162float(h0.y));
            __nv_bfloat162 l1 = __floats2bfloat162_rn(
                v.z - __bfloat162float(h1.x), v.w - __bfloat162float(h1.y));
            *(uint2*)&sm[oAhi + r * S + cq] =
                make_uint2(*(uint32_t*)&h0, *(uint32_t*)&h1);
            *(uint2*)&sm[oAlo + r * S + cq] =
                make_uint2(*(uint32_t*)&l0, *(uint32_t*)&l1);
        }
        #pragma unroll
        for (int i = 0; i < BITER; i++) {
            int idx = tid + i * 256;
            int r = idx >> 3, cq = (idx & 7) << 2;
            float4 v = vb[i];
            __nv_bfloat162 h0 = __floats2bfloat162_rn(v.x, v.y);
            __nv_bfloat162 h1 = __floats2bfloat162_rn(v.z, v.w);
            __nv_bfloat162 l0 = __floats2bfloat162_rn(
                v.x - __bfloat162float(h0.x), v.y - __bfloat162float(h0.y));
            __nv_bfloat162 l1 = __floats2bfloat162_rn(
                v.z - __bfloat162float(h1.x), v.w - __bfloat162float(h1.y));
            *(uint2*)&sm[oBhi + r * S + cq] =
                make_uint2(*(uint32_t*)&h0, *(uint32_t*)&h1);
            *(uint2*)&sm[oBlo + r * S + cq] =
                make_uint2(*(uint32_t*)&l0, *(uint32_t*)&l1);
        }
    };
    auto compute = [&](int buf) {
        const int oAhi = buf * PERBUF;
        const int oAlo = oAhi + BM * S;
        const int oBhi = oAhi + 2 * BM * S;
        const int oBlo = oBhi + BN * S;
        #pragma unroll
        for (int s = 0; s < 3; s++) {
            const int ao = (s == 2) ? oAlo : oAhi;
            const int bo = (s == 1) ? oBlo : oBhi;
            #pragma unroll
            for (int kk = 0; kk < 32; kk += 16) {
                uint32_t af[MT][4];
                #pragma unroll
                for (int mi = 0; mi < MT; mi++) {
                    uint32_t addr = sb + (uint32_t)(ao +
                        (wm0 + mi * 16 + lA_r) * S + kk + lA_c) * 2;
                    ldsm4(af[mi][0], af[mi][1], af[mi][2], af[mi][3], addr);
                }
                uint32_t bf[NT / 2][4];
                #pragma unroll
                for (int nj = 0; nj < NT / 2; nj++) {
                    uint32_t addr = sb + (uint32_t)(bo +
                        (wn0 + nj * 16 + lB_r) * S + kk + lB_c) * 2;
                    ldsm4(bf[nj][0], bf[nj][1], bf[nj][2], bf[nj][3], addr);
                }
                #pragma unroll
                for (int mi = 0; mi < MT; mi++)
                    #pragma unroll
                    for (int ni = 0; ni < NT; ni++)
                        mma_bf16(acc[mi][ni],
                                 af[mi][0], af[mi][1], af[mi][2], af[mi][3],
                                 bf[ni >> 1][(ni & 1) * 2],
                                 bf[ni >> 1][(ni & 1) * 2 + 1]);
            }
        }
    };

    // ---- pipeline ----
    loadG(0);
    storeS(0);
    __syncthreads();
    int cur = 0;
    const int KT = K / 32;
    for (int kt = 0; kt < KT; kt++) {
        bool has = (kt + 1) < KT;
        if (has) loadG((kt + 1) * 32);
        compute(cur);
        if (has) {
            storeS(cur ^ 1);
            __syncthreads();
            cur ^= 1;
        }
    }

    // ---- epilogue ----
    #pragma unroll
    for (int mi = 0; mi < MT; mi++) {
        #pragma unroll
        for (int ni = 0; ni < NT; ni++) {
            int row = bm + wm0 + mi * 16 + (lane >> 2);
            int col = bn + wn0 + ni * 8 + (lane & 3) * 2;
            float2 v0 = make_float2(acc[mi][ni][0], acc[mi][ni][1]);
            float2 v1 = make_float2(acc[mi][ni][2], acc[mi][ni][3]);
            if (RESID) {
                float2 r0 = *(const float2*)&resid[(size_t)row * ldc + col];
                float2 r1 = *(const float2*)&resid[(size_t)(row + 8) * ldc + col];
                v0.x += r0.x; v0.y += r0.y;
                v1.x += r1.x; v1.y += r1.y;
            }
            *(float2*)&C[(size_t)row * ldc + col] = v0;
            *(float2*)&C[(size_t)(row + 8) * ldc + col] = v1;
        }
    }
}

// ---------------- FFMA2 SGEMM (G2 split-K) ----------------
template<int BN, int TN, bool ATRANS, bool RESID, bool NGUARD>
__global__ __launch_bounds__(256, 2)
void sgemm(const float* __restrict__ A, int lda,
           const float* __restrict__ B, int ldb,
           float* __restrict__ C, int ldc,
           int M, int N, int Ks,
           const float* __restrict__ resid)
{
    constexpr int BM = 128, BK = 8, TM = 8;
    __shared__ __align__(16) float As[2][BK][BM + 4];
    __shared__ __align__(16) float Bs[2][BK][BN + 4];

    const int tid = threadIdx.x;
    const int bm = blockIdx.y * BM;
    const int bn = blockIdx.x * BN;
    const int z  = blockIdx.z;
    const int kbeg = z * Ks, kend = kbeg + Ks;
    C += (size_t)z * M * ldc;

    const int tx = tid & 15;
    const int ty = tid >> 4;
    const int m0 = ty * 4;
    const int n0 = tx * 4;

    const int a_row = tid >> 1;
    const int a_kq  = (tid & 1) << 2;
    const int at_k  = tid >> 5;
    const int at_m  = (tid & 31) << 2;

    const int b_row = (BN == 128) ? (tid >> 1) : (tid >> 2);
    const int b_kq  = (BN == 128) ? ((tid & 1) << 2) : ((tid & 3) << 1);

    unsigned long long acc2[TM][TN / 2];
    #pragma unroll
    for (int i = 0; i < TM; i++)
        #pragma unroll
        for (int j = 0; j < TN / 2; j++) acc2[i][j] = 0ull;

    float4 ra; float4 rb4; float2 rb2;

    auto loadA = [&](int k) {
        if (!ATRANS) ra = *(const float4*)&A[(bm + a_row) * lda + k + a_kq];
        else         ra = *(const float4*)&A[(k + at_k) * lda + bm + at_m];
    };
    auto loadB = [&](int k) {
        if (BN == 128) {
            if (NGUARD && bn + b_row >= N) rb4 = make_float4(0.f,0.f,0.f,0.f);
            else rb4 = *(const float4*)&B[(bn + b_row) * ldb + k + b_kq];
        } else {
            if (NGUARD && bn + b_row >= N) rb2 = make_float2(0.f,0.f);
            else rb2 = *(const float2*)&B[(bn + b_row) * ldb + k + b_kq];
        }
    };
    auto stA = [&](int buf) {
        if (!ATRANS) {
            As[buf][a_kq + 0][a_row] = ra.x; As[buf][a_kq + 1][a_row] = ra.y;
            As[buf][a_kq + 2][a_row] = ra.z; As[buf][a_kq + 3][a_row] = ra.w;
        } else {
            *(float4*)&As[buf][at_k][at_m] = ra;
        }
    };
    auto stB = [&](int buf) {
        if (BN == 128) {
            Bs[buf][b_kq + 0][b_row] = rb4.x; Bs[buf][b_kq + 1][b_row] = rb4.y;
            Bs[buf][b_kq + 2][b_row] = rb4.z; Bs[buf][b_kq + 3][b_row] = rb4.w;
        } else {
            Bs[buf][b_kq + 0][b_row] = rb2.x; Bs[buf][b_kq + 1][b_row] = rb2.y;
        }
    };

    loadA(kbeg); loadB(kbeg);
    stA(0); stB(0);
    __syncthreads();

    int cur = 0;
    for (int k0 = kbeg; k0 < kend; k0 += BK) {
        const int kn = k0 + BK;
        const bool has = kn < kend;
        if (has) { loadA(kn); loadB(kn); }
        #pragma unroll
        for (int kk = 0; kk < BK; kk++) {
            float4 a0 = *(const float4*)&As[cur][kk][m0];
            float4 a1 = *(const float4*)&As[cur][kk][m0 + 64];
            unsigned long long aa[TM];
            aa[0] = pack2(a0.x, a0.x); aa[1] = pack2(a0.y, a0.y);
            aa[2] = pack2(a0.z, a0.z); aa[3] = pack2(a0.w, a0.w);
            aa[4] = pack2(a1.x, a1.x); aa[5] = pack2(a1.y, a1.y);
            aa[6] = pack2(a1.z, a1.z); aa[7] = pack2(a1.w, a1.w);
            unsigned long long bb[TN / 2];
            {
                ulonglong2 b0 = *(const ulonglong2*)&Bs[cur][kk][n0];
                bb[0] = b0.x; bb[1] = b0.y;
                if (TN == 8) {
                    ulonglong2 b1 = *(const ulonglong2*)&Bs[cur][kk][n0 + 64];
                    bb[2] = b1.x; bb[3] = b1.y;
                }
            }
            #pragma unroll
            for (int i = 0; i < TM; i++)
                #pragma unroll
                for (int j = 0; j < TN / 2; j++)
                    acc2[i][j] = fma2(aa[i], bb[j], acc2[i][j]);
        }
        if (has) {
            cur ^= 1;
            stA(cur); stB(cur);
            __syncthreads();
        }
    }

    #pragma unroll
    for (int half = 0; half < 2; half++) {
        #pragma unroll
        for (int i = 0; i < 4; i++) {
            int m = bm + half * 64 + m0 + i;
            int ai = half * 4 + i;
            #pragma unroll
            for (int jq = 0; jq < TN / 4; jq++) {
                int n = bn + jq * 64 + n0;
                if (NGUARD && n >= N) continue;
                float2 v0 = unpack2(acc2[ai][jq * 2 + 0]);
                float2 v1 = unpack2(acc2[ai][jq * 2 + 1]);
                float4 v = make_float4(v0.x, v0.y, v1.x, v1.y);
                if (RESID) {
                    float4 r = *(const float4*)&resid[m * ldc + n];
                    v.x += r.x; v.y += r.y; v.z += r.z; v.w += r.w;
                }
                *(float4*)&C[m * ldc + n] = v;
            }
        }
    }
}

// deterministic reduce of the 4 split-K partials
__global__ void reduce4_kernel()
{
    int i = (blockIdx.x * 256 + threadIdx.x) * 4;
    const int TOT = SEQ * DBCCOLS;
    float4 a = *(const float4*)&g_dbcp[0 * TOT + i];
    float4 b = *(const float4*)&g_dbcp[1 * TOT + i];
    float4 c = *(const float4*)&g_dbcp[2 * TOT + i];
    float4 d = *(const float4*)&g_dbcp[3 * TOT + i];
    float4 o;
    o.x = (a.x + b.x) + (c.x + d.x);
    o.y = (a.y + b.y) + (c.y + d.y);
    o.z = (a.z + b.z) + (c.z + d.z);
    o.w = (a.w + b.w) + (c.w + d.w);
    *(float4*)&g_dbc[i] = o;
}

// ---------------- depthwise conv + silu + transposes ----------------
__global__ __launch_bounds__(256)
void conv_kernel(const float* __restrict__ cw, const float* __restrict__ cb)
{
    __shared__ float sxz[35][33];
    __shared__ float sxi[32][33];
    __shared__ float szs[32][33];
    int t0 = blockIdx.x * 32, c0 = blockIdx.y * 32;
    int tid = threadIdx.x;

    for (int i = tid; i < 35 * 32; i += 256) {
        int r = i >> 5, c = i & 31;
        int gt = t0 + r - 3;
        sxz[r][c] = (gt >= 0) ? g_xz[gt * XZCOLS + c0 + c] : 0.0f;
    }
    for (int i = tid; i < 32 * 32; i += 256) {
        int r = i >> 5, c = i & 31;
        float z = g_xz[(t0 + r) * XZCOLS + DINNER + c0 + c];
        szs[r][c] = siluf(z);
    }
    __syncthreads();

    int cl = tid & 31, tq = tid >> 5;
    float4 w = *(const float4*)&cw[(c0 + cl) * 4];
    float bb = cb[c0 + cl];
    #pragma unroll
    for (int s = 0; s < 4; s++) {
        int tl = tq + s * 8;
        float v = sxz[tl + 0][cl] * w.x + sxz[tl + 1][cl] * w.y +
                  sxz[tl + 2][cl] * w.z + sxz[tl + 3][cl] * w.w + bb;
        v = siluf(v);
        g_xi[(t0 + tl) * DINNER + c0 + cl] = v;
        sxi[tl][cl] = v;
    }
    __syncthreads();

    int tl2 = tid & 31, cq = tid >> 5;
    #pragma unroll
    for (int s = 0; s < 4; s++) {
        int cl2 = cq + s * 8;
        g_xiT[(c0 + cl2) * SEQ + t0 + tl2] = sxi[tl2][cl2];
        g_zsT[(c0 + cl2) * SEQ + t0 + tl2] = szs[tl2][cl2];
    }
}

// ---------------- selective scan: deferred butterfly reduction ----------------
__global__ __launch_bounds__(256)
void scan_kernel(const float* __restrict__ Wdt, const float* __restrict__ bdt,
                 const float* __restrict__ A_log, const float* __restrict__ Dp)
{
    __shared__ __align__(16) float sD[32][164];
    const unsigned FULL = 0xffffffffu;
    int tid = threadIdx.x, lane = tid & 31, w = tid >> 5;
    int d = blockIdx.x * 8 + w;

    float wv  = Wdt[d * DTRANK + lane];
    float bd  = bdt[d];
    float A0  = -expf(A_log[d * DSTATE + lane]);
    float A1  = -expf(A_log[d * DSTATE + 32 + lane]);
    float d32 = A1 - A0;
    bool uni  = __all_sync(FULL, __shfl_sync(FULL, d32, 0) == d32);
    float Dpd = Dp[d];
    float h0 = 0.f, h1 = 0.f;

    const float* xT = g_xiT + d * SEQ;
    const float* zT = g_zsT + d * SEQ;

    for (int t0 = 0; t0 < SEQ; t0 += 32) {
        __syncthreads();
        for (int i = tid; i < 32 * 40; i += 256) {
            int r = i / 40, q = (i % 40) * 4;
            *(float4*)&sD[r][q] = *(const float4*)&g_dbc[(t0 + r) * DBCCOLS + q];
        }
        __syncthreads();

        float accd = bd;
        #pragma unroll
        for (int r = 0; r < DTRANK; r++)
            accd = fmaf(sD[lane][r], __shfl_sync(FULL, wv, r), accd);
        float myD = softplusf(accd);

        float myX   = xT[t0 + lane];
        float myZ   = zT[t0 + lane];
        float myDux = myD * myX;
        float myE32 = __expf(myD * d32);

        float p[32];
        #pragma unroll
        for (int i = 0; i < 32; i++) {
            float du  = __shfl_sync(FULL, myD,   i);
            float dux = __shfl_sync(FULL, myDux, i);
            float e0  = __expf(du * A0);
            float e1;
            if (uni) e1 = e0 * __shfl_sync(FULL, myE32, i);
            else     e1 = __expf(du * A1);
            h0 = fmaf(e0, h0, dux * sD[i][32 + lane]);
            h1 = fmaf(e1, h1, dux * sD[i][64 + lane]);
            p[i] = fmaf(h0, sD[i][96 + lane], h1 * sD[i][128 + lane]);
        }

        #pragma unroll
        for (int o = 16; o >= 1; o >>= 1) {
            bool hi = (lane & o) != 0;
            #pragma unroll
            for (int jj = 0; jj < o; jj++) {
                float keep = hi ? p[o + jj] : p[jj];
                float send = hi ? p[jj] : p[o + jj];
                p[jj] = keep + __shfl_xor_sync(FULL, send, o);
            }
        }

        g_y[(size_t)(t0 + lane) * DINNER + d] = (p[0] + Dpd * myX) * myZ;
    }
}

// ---------------- launcher ----------------
extern "C" void kernel_launch(void* const* d_in, const int* in_sizes, int n_in,
                              void* d_out, int out_size)
{
    const float* x      = (const float*)d_in[0];
    const float* ln_g   = (const float*)d_in[1];
    const float* ln_b   = (const float*)d_in[2];
    const float* Win    = (const float*)d_in[3];
    const float* conv_w = (const float*)d_in[4];
    const float* conv_b = (const float*)d_in[5];
    const float* Wx     = (const float*)d_in[6];
    const float* Wdt    = (const float*)d_in[7];
    const float* bdt    = (const float*)d_in[8];
    const float* A_log  = (const float*)d_in[9];
    const float* Dp     = (const float*)d_in[10];
    const float* Wout   = (const float*)d_in[11];
    float* out = (float*)d_out;

    float *p_xn, *p_xz, *p_xi, *p_dbcp, *p_y;
    cudaGetSymbolAddress((void**)&p_xn,   g_xn);
    cudaGetSymbolAddress((void**)&p_xz,   g_xz);
    cudaGetSymbolAddress((void**)&p_xi,   g_xi);
    cudaGetSymbolAddress((void**)&p_dbcp, g_dbcp);
    cudaGetSymbolAddress((void**)&p_y,    g_y);

    // dynamic smem: 2 bufs * (2*BM*40 + 2*BN*40) bf16 * 2 B
    const int smem_g1 = 2 * (2 * 128 * 40 + 2 * 128 * 40) * 2;  // 81920
    const int smem_g4 = 2 * (2 * 64 * 40 + 2 * 128 * 40) * 2;   // 61440
    cudaFuncSetAttribute(mma_gemm<128, 128, false>,
        cudaFuncAttributeMaxDynamicSharedMemorySize, smem_g1);
    cudaFuncSetAttribute(mma_gemm<64, 128, true>,
        cudaFuncAttributeMaxDynamicSharedMemorySize, smem_g4);

    // 1. LayerNorm
    ln_kernel<<<SEQ, 256>>>(x, ln_g, ln_b, p_xn);

    // 2. xz = xn @ Win^T  [2048 x 2048 x 512]  split-bf16 HMMA
    mma_gemm<128, 128, false><<<dim3(XZCOLS / 128, SEQ / 128), 256, smem_g1>>>(
        p_xn, DMODEL, Win, DMODEL, p_xz, XZCOLS, DMODEL, nullptr);

    // 3. conv + silu + transposes
    conv_kernel<<<dim3(SEQ / 32, DINNER / 32), 256>>>(conv_w, conv_b);

    // 4. dbc = xi @ Wx^T  [2048 x 160 x 1024]  FFMA2 split-K=4 + reduce
    sgemm<64, 4, false, false, true><<<dim3(3, SEQ / 128, NSPLIT), 256>>>(
        p_xi, DINNER, Wx, DINNER, p_dbcp, DBCCOLS, SEQ, DBCCOLS,
        DINNER / NSPLIT, nullptr);
    reduce4_kernel<<<SEQ * DBCCOLS / 1024, 256>>>();

    // 5+6. selective scan (fused delta) -> y row-major
    scan_kernel<<<DINNER / 8, 256>>>(Wdt, bdt, A_log, Dp);

    // 7. out = y @ Wout^T + x  [2048 x 512 x 1024]  split-bf16 HMMA + resid
    mma_gemm<64, 128, true><<<dim3(DMODEL / 128, SEQ / 64), 256, smem_g4>>>(
        p_y, DINNER, Wout, DINNER, out, DMODEL, DINNER, x);
}

// round 7
// speedup vs baseline: 2.4138x; 1.4919x over previous
#include <cuda_runtime.h>
#include <cuda_bf16.h>
#include <math.h>
#include <stdint.h>

// ---------------- problem constants ----------------
#define SEQ     2048
#define DMODEL  512
#define DINNER  1024
#define DSTATE  64
#define DTRANK  32
#define DCONV   4
#define XZCOLS  (2*DINNER)          // 2048
#define DBCCOLS (DTRANK + 2*DSTATE) // 160
#define NSPLIT  4
#define NC      8                   // scan chunks
#define LC      (SEQ/NC)            // 256 timesteps per chunk

// ---------------- scratch (device globals; no allocation) ----------------
__device__ float g_xn    [SEQ*DMODEL];
__device__ float g_xz    [SEQ*XZCOLS];
__device__ float g_xi    [SEQ*DINNER];
__device__ float g_xiT   [DINNER*SEQ];
__device__ float g_zsT   [DINNER*SEQ];
__device__ float g_dbcp  [NSPLIT*SEQ*DBCCOLS];
__device__ float g_dbc   [SEQ*DBCCOLS];
__device__ float g_dT    [DINNER*SEQ];        // delta^T (softplus applied)
__device__ float g_S     [DINNER*NC];         // per-chunk sum of delta
__device__ float g_hend  [NC*DINNER*DSTATE];  // pass1 local final states
__device__ float g_hstart[NC*DINNER*DSTATE];  // pass2 chunk initial states
__device__ float g_y     [SEQ*DINNER];        // scan output, row-major [t][c]

// ---------------- helpers ----------------
__device__ __forceinline__ float siluf(float x) { return x / (1.0f + __expf(-x)); }
__device__ __forceinline__ float softplusf(float x) {
    return (x > 15.0f) ? x : log1pf(__expf(x));
}
__device__ __forceinline__ uint32_t smem_u32(const void* p) {
    uint32_t a;
    asm("{ .reg .u64 t; cvta.to.shared.u64 t, %1; cvt.u32.u64 %0, t; }"
        : "=r"(a) : "l"(p));
    return a;
}
__device__ __forceinline__ void ldsm4(uint32_t& r0, uint32_t& r1,
                                      uint32_t& r2, uint32_t& r3, uint32_t addr) {
    asm volatile("ldmatrix.sync.aligned.m8n8.x4.shared.b16 {%0,%1,%2,%3}, [%4];"
                 : "=r"(r0), "=r"(r1), "=r"(r2), "=r"(r3) : "r"(addr));
}
__device__ __forceinline__ void mma_bf16(float* c, uint32_t a0, uint32_t a1,
                                         uint32_t a2, uint32_t a3,
                                         uint32_t b0, uint32_t b1) {
    asm volatile(
        "mma.sync.aligned.m16n8k16.row.col.f32.bf16.bf16.f32 "
        "{%0,%1,%2,%3}, {%4,%5,%6,%7}, {%8,%9}, {%0,%1,%2,%3};"
        : "+f"(c[0]), "+f"(c[1]), "+f"(c[2]), "+f"(c[3])
        : "r"(a0), "r"(a1), "r"(a2), "r"(a3), "r"(b0), "r"(b1));
}

// ---------------- LayerNorm: one block per token ----------------
__global__ void ln_kernel(const float* __restrict__ x,
                          const float* __restrict__ g,
                          const float* __restrict__ b,
                          float* __restrict__ xn)
{
    int t   = blockIdx.x;
    int tid = threadIdx.x;
    const float* xr = x + t * DMODEL;
    float2 v = *(const float2*)&xr[tid * 2];
    float s = v.x + v.y;
    float q = v.x * v.x + v.y * v.y;
    #pragma unroll
    for (int o = 16; o > 0; o >>= 1) {
        s += __shfl_xor_sync(0xffffffffu, s, o);
        q += __shfl_xor_sync(0xffffffffu, q, o);
    }
    __shared__ float ss[8], qq[8];
    int lane = tid & 31, w = tid >> 5;
    if (lane == 0) { ss[w] = s; qq[w] = q; }
    __syncthreads();
    s = 0.f; q = 0.f;
    #pragma unroll
    for (int i = 0; i < 8; i++) { s += ss[i]; q += qq[i]; }
    float mu  = s * (1.0f / DMODEL);
    float var = q * (1.0f / DMODEL) - mu * mu;
    float r   = rsqrtf(var + 1e-5f);
    float2 gg = *(const float2*)&g[tid * 2];
    float2 bb = *(const float2*)&b[tid * 2];
    float2 o;
    o.x = (v.x - mu) * r * gg.x + bb.x;
    o.y = (v.y - mu) * r * gg.y + bb.y;
    *(float2*)&xn[t * DMODEL + tid * 2] = o;
}

// ---------------- split-bf16 HMMA GEMM (mma.sync, baseline PTX) ----------------
// C[m][n] = sum_k A[m][k]*B[n][k]; A row-major [M][K], B row-major [N][K].
// D = Ahi*Bhi + Ahi*Blo + Alo*Bhi, fp32 accum. BK=32, smem rows padded to 40
// bf16 -> conflict-free ldmatrix. 8 warps in 2(m) x 4(n) grid.
// K param = per-split depth; kbeg = blockIdx.z*K; split partial at C+z*M*ldc.
// EPI: 0 none, 1 resid add (ep = resid, C layout), 2 softplus(acc + ep[row]).
// NGUARD: clamp B rows and skip C cols >= N.
template<int BM, int BN, int EPI, bool NGUARD>
__global__ __launch_bounds__(256)
void mma_gemm(const float* __restrict__ A, int lda,
              const float* __restrict__ B, int ldb,
              float* __restrict__ C, int ldc,
              int M, int N, int K, const float* __restrict__ ep)
{
    constexpr int S = 40;
    constexpr int MT = (BM / 2) / 16;
    constexpr int NT = (BN / 4) / 8;
    constexpr int AITER = BM / 32;
    constexpr int BITER = BN / 32;
    constexpr int PERBUF = 2 * BM * S + 2 * BN * S;

    extern __shared__ __align__(16) __nv_bfloat16 sm[];
    const uint32_t sb = smem_u32(sm);

    const int tid = threadIdx.x, lane = tid & 31, wid = tid >> 5;
    const int bm = blockIdx.y * BM, bn = blockIdx.x * BN;
    const int z = blockIdx.z;
    const int kbeg = z * K;
    C += (size_t)z * M * ldc;
    const int wm0 = (wid & 1) * (BM / 2);
    const int wn0 = (wid >> 1) * (BN / 4);

    const int lA_r = lane & 15;
    const int lA_c = (lane >> 4) << 3;
    const int lB_r = (lane & 7) + ((lane >> 4) << 3);
    const int lB_c = ((lane >> 3) & 1) << 3;

    float acc[MT][NT][4];
    #pragma unroll
    for (int i = 0; i < MT; i++)
        #pragma unroll
        for (int j = 0; j < NT; j++)
            #pragma unroll
            for (int q = 0; q < 4; q++) acc[i][j][q] = 0.0f;

    float4 va[AITER], vb[BITER];

    auto loadG = [&](int k0) {
        #pragma unroll
        for (int i = 0; i < AITER; i++) {
            int idx = tid + i * 256;
            int r = idx >> 3, cq = (idx & 7) << 2;
            va[i] = *(const float4*)&A[(size_t)(bm + r) * lda + k0 + cq];
        }
        #pragma unroll
        for (int i = 0; i < BITER; i++) {
            int idx = tid + i * 256;
            int r = idx >> 3, cq = (idx & 7) << 2;
            int rr = bn + r;
            if (NGUARD) rr = min(rr, N - 1);
            vb[i] = *(const float4*)&B[(size_t)rr * ldb + k0 + cq];
        }
    };
    auto storeS = [&](int buf) {
        const int oAhi = buf * PERBUF;
        const int oAlo = oAhi + BM * S;
        const int oBhi = oAhi + 2 * BM * S;
        const int oBlo = oBhi + BN * S;
        #pragma unroll
        for (int i = 0; i < AITER; i++) {
            int idx = tid + i * 256;
            int r = idx >> 3, cq = (idx & 7) << 2;
            float4 v = va[i];
            __nv_bfloat162 h0 = __floats2bfloat162_rn(v.x, v.y);
            __nv_bfloat162 h1 = __floats2bfloat162_rn(v.z, v.w);
            __nv_bfloat162 l0 = __floats2bfloat162_rn(
                v.x - __bfloat162float(h0.x), v.y - __bfloat162float(h0.y));
            __nv_bfloat162 l1 = __floats2bfloat162_rn(
                v.z - __bfloat162float(h1.x), v.w - __bfloat162float(h1.y));
            *(uint2*)&sm[oAhi + r * S + cq] =
                make_uint2(*(uint32_t*)&h0, *(uint32_t*)&h1);
            *(uint2*)&sm[oAlo + r * S + cq] =
                make_uint2(*(uint32_t*)&l0, *(uint32_t*)&l1);
        }
        #pragma unroll
        for (int i = 0; i < BITER; i++) {
            int idx = tid + i * 256;
            int r = idx >> 3, cq = (idx & 7) << 2;
            float4 v = vb[i];
            __nv_bfloat162 h0 = __floats2bfloat162_rn(v.x, v.y);
            __nv_bfloat162 h1 = __floats2bfloat162_rn(v.z, v.w);
            __nv_bfloat162 l0 = __floats2bfloat162_rn(
                v.x - __bfloat162float(h0.x), v.y - __bfloat162float(h0.y));
            __nv_bfloat162 l1 = __floats2bfloat162_rn(
                v.z - __bfloat162float(h1.x), v.w - __bfloat162float(h1.y));
            *(uint2*)&sm[oBhi + r * S + cq] =
                make_uint2(*(uint32_t*)&h0, *(uint32_t*)&h1);
            *(uint2*)&sm[oBlo + r * S + cq] =
                make_uint2(*(uint32_t*)&l0, *(uint32_t*)&l1);
        }
    };
    auto compute = [&](int buf) {
        const int oAhi = buf * PERBUF;
        const int oAlo = oAhi + BM * S;
        const int oBhi = oAhi + 2 * BM * S;
        const int oBlo = oBhi + BN * S;
        #pragma unroll
        for (int s = 0; s < 3; s++) {
            const int ao = (s == 2) ? oAlo : oAhi;
            const int bo = (s == 1) ? oBlo : oBhi;
            #pragma unroll
            for (int kk = 0; kk < 32; kk += 16) {
                uint32_t af[MT][4];
                #pragma unroll
                for (int mi = 0; mi < MT; mi++) {
                    uint32_t addr = sb + (uint32_t)(ao +
                        (wm0 + mi * 16 + lA_r) * S + kk + lA_c) * 2;
                    ldsm4(af[mi][0], af[mi][1], af[mi][2], af[mi][3], addr);
                }
                uint32_t bf[NT / 2][4];
                #pragma unroll
                for (int nj = 0; nj < NT / 2; nj++) {
                    uint32_t addr = sb + (uint32_t)(bo +
                        (wn0 + nj * 16 + lB_r) * S + kk + lB_c) * 2;
                    ldsm4(bf[nj][0], bf[nj][1], bf[nj][2], bf[nj][3], addr);
                }
                #pragma unroll
                for (int mi = 0; mi < MT; mi++)
                    #pragma unroll
                    for (int ni = 0; ni < NT; ni++)
                        mma_bf16(acc[mi][ni],
                                 af[mi][0], af[mi][1], af[mi][2], af[mi][3],
                                 bf[ni >> 1][(ni & 1) * 2],
                                 bf[ni >> 1][(ni & 1) * 2 + 1]);
            }
        }
    };

    loadG(kbeg);
    storeS(0);
    __syncthreads();
    int cur = 0;
    const int KT = K / 32;
    for (int kt = 0; kt < KT; kt++) {
        bool has = (kt + 1) < KT;
        if (has) loadG(kbeg + (kt + 1) * 32);
        compute(cur);
        if (has) {
            storeS(cur ^ 1);
            __syncthreads();
            cur ^= 1;
        }
    }

    #pragma unroll
    for (int mi = 0; mi < MT; mi++) {
        #pragma unroll
        for (int ni = 0; ni < NT; ni++) {
            int colb = bn + wn0 + ni * 8;
            if (NGUARD && colb >= N) continue;
            int row = bm + wm0 + mi * 16 + (lane >> 2);
            int col = colb + (lane & 3) * 2;
            float2 v0 = make_float2(acc[mi][ni][0], acc[mi][ni][1]);
            float2 v1 = make_float2(acc[mi][ni][2], acc[mi][ni][3]);
            if (EPI == 1) {
                float2 r0 = *(const float2*)&ep[(size_t)row * ldc + col];
                float2 r1 = *(const float2*)&ep[(size_t)(row + 8) * ldc + col];
                v0.x += r0.x; v0.y += r0.y;
                v1.x += r1.x; v1.y += r1.y;
            } else if (EPI == 2) {
                float b0 = ep[row], b1 = ep[row + 8];
                v0.x = softplusf(v0.x + b0); v0.y = softplusf(v0.y + b0);
                v1.x = softplusf(v1.x + b1); v1.y = softplusf(v1.y + b1);
            }
            *(float2*)&C[(size_t)row * ldc + col] = v0;
            *(float2*)&C[(size_t)(row + 8) * ldc + col] = v1;
        }
    }
}

// deterministic reduce of the 4 split-K partials
__global__ void reduce4_kernel()
{
    int i = (blockIdx.x * 256 + threadIdx.x) * 4;
    const int TOT = SEQ * DBCCOLS;
    float4 a = *(const float4*)&g_dbcp[0 * TOT + i];
    float4 b = *(const float4*)&g_dbcp[1 * TOT + i];
    float4 c = *(const float4*)&g_dbcp[2 * TOT + i];
    float4 d = *(const float4*)&g_dbcp[3 * TOT + i];
    float4 o;
    o.x = (a.x + b.x) + (c.x + d.x);
    o.y = (a.y + b.y) + (c.y + d.y);
    o.z = (a.z + b.z) + (c.z + d.z);
    o.w = (a.w + b.w) + (c.w + d.w);
    *(float4*)&g_dbc[i] = o;
}

// ---------------- depthwise conv + silu + transposes ----------------
__global__ __launch_bounds__(256)
void conv_kernel(const float* __restrict__ cw, const float* __restrict__ cb)
{
    __shared__ float sxz[35][33];
    __shared__ float sxi[32][33];
    __shared__ float szs[32][33];
    int t0 = blockIdx.x * 32, c0 = blockIdx.y * 32;
    int tid = threadIdx.x;

    for (int i = tid; i < 35 * 32; i += 256) {
        int r = i >> 5, c = i & 31;
        int gt = t0 + r - 3;
        sxz[r][c] = (gt >= 0) ? g_xz[gt * XZCOLS + c0 + c] : 0.0f;
    }
    for (int i = tid; i < 32 * 32; i += 256) {
        int r = i >> 5, c = i & 31;
        float z = g_xz[(t0 + r) * XZCOLS + DINNER + c0 + c];
        szs[r][c] = siluf(z);
    }
    __syncthreads();

    int cl = tid & 31, tq = tid >> 5;
    float4 w = *(const float4*)&cw[(c0 + cl) * 4];
    float bb = cb[c0 + cl];
    #pragma unroll
    for (int s = 0; s < 4; s++) {
        int tl = tq + s * 8;
        float v = sxz[tl + 0][cl] * w.x + sxz[tl + 1][cl] * w.y +
                  sxz[tl + 2][cl] * w.z + sxz[tl + 3][cl] * w.w + bb;
        v = siluf(v);
        g_xi[(t0 + tl) * DINNER + c0 + cl] = v;
        sxi[tl][cl] = v;
    }
    __syncthreads();

    int tl2 = tid & 31, cq = tid >> 5;
    #pragma unroll
    for (int s = 0; s < 4; s++) {
        int cl2 = cq + s * 8;
        g_xiT[(c0 + cl2) * SEQ + t0 + tl2] = sxi[tl2][cl2];
        g_zsT[(c0 + cl2) * SEQ + t0 + tl2] = szs[tl2][cl2];
    }
}

// ---------------- chunked scan, pass 1: local h-scan per chunk ----------------
// warp = channel d, blockIdx.y = chunk. h from 0 over LC steps; emits
// h_end[d][n] and S = sum(delta) per chunk. No y, no C reads.
__global__ __launch_bounds__(256)
void scan_pass1(const float* __restrict__ A_log)
{
    __shared__ __align__(16) float sB[32][68];
    const unsigned FULL = 0xffffffffu;
    int tid = threadIdx.x, lane = tid & 31, w = tid >> 5;
    int d = blockIdx.x * 8 + w;
    int c = blockIdx.y;

    float A0  = -expf(A_log[d * DSTATE + lane]);
    float A1  = -expf(A_log[d * DSTATE + 32 + lane]);
    float d32 = A1 - A0;
    bool uni  = __all_sync(FULL, __shfl_sync(FULL, d32, 0) == d32);
    float h0 = 0.f, h1 = 0.f, ssum = 0.f;

    const float* xT  = g_xiT + (size_t)d * SEQ;
    const float* dTp = g_dT  + (size_t)d * SEQ;
    const int tbeg = c * LC;

    for (int t0 = tbeg; t0 < tbeg + LC; t0 += 32) {
        __syncthreads();
        for (int i = tid; i < 32 * 16; i += 256) {
            int r = i >> 4, q = (i & 15) << 2;
            *(float4*)&sB[r][q] =
                *(const float4*)&g_dbc[(size_t)(t0 + r) * DBCCOLS + 32 + q];
        }
        __syncthreads();

        float myD   = dTp[t0 + lane];
        float myDux = myD * xT[t0 + lane];
        float myE32 = __expf(myD * d32);
        ssum += myD;

        #pragma unroll 8
        for (int i = 0; i < 32; i++) {
            float du  = __shfl_sync(FULL, myD,   i);
            float dux = __shfl_sync(FULL, myDux, i);
            float e0  = __expf(du * A0);
            float e1  = uni ? e0 * __shfl_sync(FULL, myE32, i)
                            : __expf(du * A1);
            h0 = fmaf(e0, h0, dux * sB[i][lane]);
            h1 = fmaf(e1, h1, dux * sB[i][32 + lane]);
        }
    }
    float S = ssum;
    #pragma unroll
    for (int o = 16; o > 0; o >>= 1) S += __shfl_xor_sync(FULL, S, o);
    if (lane == 0) g_S[d * NC + c] = S;
    float* he = g_hend + ((size_t)c * DINNER + d) * DSTATE;
    he[lane] = h0;
    he[32 + lane] = h1;
}

// ---------------- pass 2: chain chunk-initial states ----------------
__global__ void scan_pass2(const float* __restrict__ A_log)
{
    int idx = blockIdx.x * 256 + threadIdx.x;    // 0..DINNER*DSTATE-1
    int d = idx >> 6, n = idx & 63;
    float An = -expf(A_log[d * DSTATE + n]);
    float h = 0.f;
    #pragma unroll
    for (int c = 0; c < NC; c++) {
        g_hstart[((size_t)c * DINNER + d) * DSTATE + n] = h;
        float E = __expf(An * g_S[d * NC + c]);
        h = fmaf(E, h, g_hend[((size_t)c * DINNER + d) * DSTATE + n]);
    }
}

// ---------------- pass 3: y-producing scan per chunk, correct init ----------------
__global__ __launch_bounds__(256)
void scan_pass3(const float* __restrict__ A_log, const float* __restrict__ Dp)
{
    __shared__ __align__(16) float sD[32][132];   // cols 32..160 of dbc (B|C)
    const unsigned FULL = 0xffffffffu;
    int tid = threadIdx.x, lane = tid & 31, w = tid >> 5;
    int d = blockIdx.x * 8 + w;
    int c = blockIdx.y;

    float A0  = -expf(A_log[d * DSTATE + lane]);
    float A1  = -expf(A_log[d * DSTATE + 32 + lane]);
    float d32 = A1 - A0;
    bool uni  = __all_sync(FULL, __shfl_sync(FULL, d32, 0) == d32);
    float Dpd = Dp[d];

    const float* hs = g_hstart + ((size_t)c * DINNER + d) * DSTATE;
    float h0 = hs[lane];
    float h1 = hs[32 + lane];

    const float* xT  = g_xiT + (size_t)d * SEQ;
    const float* zT  = g_zsT + (size_t)d * SEQ;
    const float* dTp = g_dT  + (size_t)d * SEQ;
    const int tbeg = c * LC;

    for (int t0 = tbeg; t0 < tbeg + LC; t0 += 32) {
        __syncthreads();
        for (int i = tid; i < 32 * 32; i += 256) {
            int r = i >> 5, q = (i & 31) << 2;
            *(float4*)&sD[r][q] =
                *(const float4*)&g_dbc[(size_t)(t0 + r) * DBCCOLS + 32 + q];
        }
        __syncthreads();

        float myD   = dTp[t0 + lane];
        float myX   = xT[t0 + lane];
        float myZ   = zT[t0 + lane];
        float myDux = myD * myX;
        float myE32 = __expf(myD * d32);

        float p[32];
        #pragma unroll
        for (int i = 0; i < 32; i++) {
            float du  = __shfl_sync(FULL, myD,   i);
            float dux = __shfl_sync(FULL, myDux, i);
            float e0  = __expf(du * A0);
            float e1  = uni ? e0 * __shfl_sync(FULL, myE32, i)
                            : __expf(du * A1);
            h0 = fmaf(e0, h0, dux * sD[i][lane]);
            h1 = fmaf(e1, h1, dux * sD[i][32 + lane]);
            p[i] = fmaf(h0, sD[i][64 + lane], h1 * sD[i][96 + lane]);
        }

        #pragma unroll
        for (int o = 16; o >= 1; o >>= 1) {
            bool hi = (lane & o) != 0;
            #pragma unroll
            for (int jj = 0; jj < o; jj++) {
                float keep = hi ? p[o + jj] : p[jj];
                float send = hi ? p[jj] : p[o + jj];
                p[jj] = keep + __shfl_xor_sync(FULL, send, o);
            }
        }

        g_y[(size_t)(t0 + lane) * DINNER + d] = (p[0] + Dpd * myX) * myZ;
    }
}

// ---------------- launcher ----------------
extern "C" void kernel_launch(void* const* d_in, const int* in_sizes, int n_in,
                              void* d_out, int out_size)
{
    const float* x      = (const float*)d_in[0];
    const float* ln_g   = (const float*)d_in[1];
    const float* ln_b   = (const float*)d_in[2];
    const float* Win    = (const float*)d_in[3];
    const float* conv_w = (const float*)d_in[4];
    const float* conv_b = (const float*)d_in[5];
    const float* Wx     = (const float*)d_in[6];
    const float* Wdt    = (const float*)d_in[7];
    const float* bdt    = (const float*)d_in[8];
    const float* A_log  = (const float*)d_in[9];
    const float* Dp     = (const float*)d_in[10];
    const float* Wout   = (const float*)d_in[11];
    float* out = (float*)d_out;

    float *p_xn, *p_xz, *p_xi, *p_dbcp, *p_dbc, *p_dT, *p_y;
    cudaGetSymbolAddress((void**)&p_xn,   g_xn);
    cudaGetSymbolAddress((void**)&p_xz,   g_xz);
    cudaGetSymbolAddress((void**)&p_xi,   g_xi);
    cudaGetSymbolAddress((void**)&p_dbcp, g_dbcp);
    cudaGetSymbolAddress((void**)&p_dbc,  g_dbc);
    cudaGetSymbolAddress((void**)&p_dT,   g_dT);
    cudaGetSymbolAddress((void**)&p_y,    g_y);

    const int smem_128 = 2 * (2 * 128 * 40 + 2 * 128 * 40) * 2;  // 81920
    const int smem_g2  = 2 * (2 * 128 * 40 + 2 * 64  * 40) * 2;  // 61440
    const int smem_g4  = 2 * (2 * 64  * 40 + 2 * 128 * 40) * 2;  // 61440
    cudaFuncSetAttribute(mma_gemm<128, 128, 0, false>,
        cudaFuncAttributeMaxDynamicSharedMemorySize, smem_128);
    cudaFuncSetAttribute(mma_gemm<128, 64, 0, true>,
        cudaFuncAttributeMaxDynamicSharedMemorySize, smem_g2);
    cudaFuncSetAttribute(mma_gemm<128, 128, 2, false>,
        cudaFuncAttributeMaxDynamicSharedMemorySize, smem_128);
    cudaFuncSetAttribute(mma_gemm<64, 128, 1, false>,
        cudaFuncAttributeMaxDynamicSharedMemorySize, smem_g4);

    // 1. LayerNorm
    ln_kernel<<<SEQ, 256>>>(x, ln_g, ln_b, p_xn);

    // 2. xz = xn @ Win^T  [2048 x 2048 x 512]  HMMA
    mma_gemm<128, 128, 0, false><<<dim3(16, 16), 256, smem_128>>>(
        p_xn, DMODEL, Win, DMODEL, p_xz, XZCOLS, SEQ, XZCOLS, DMODEL, nullptr);

    // 3. conv + silu + transposes
    conv_kernel<<<dim3(SEQ / 32, DINNER / 32), 256>>>(conv_w, conv_b);

    // 4. dbc = xi @ Wx^T  [2048 x 160 x 1024]  HMMA split-K=4 + reduce
    mma_gemm<128, 64, 0, true><<<dim3(3, 16, NSPLIT), 256, smem_g2>>>(
        p_xi, DINNER, Wx, DINNER, p_dbcp, DBCCOLS, SEQ, DBCCOLS,
        DINNER / NSPLIT, nullptr);
    reduce4_kernel<<<SEQ * DBCCOLS / 1024, 256>>>();

    // 5. delta^T = softplus(Wdt @ dt^T + bdt)  [1024 x 2048 x 32]  HMMA
    mma_gemm<128, 128, 2, false><<<dim3(16, 8), 256, smem_128>>>(
        Wdt, DTRANK, p_dbc, DBCCOLS, p_dT, SEQ, DINNER, SEQ, DTRANK, bdt);

    // 6. chunked selective scan
    scan_pass1<<<dim3(DINNER / 8, NC), 256>>>(A_log);
    scan_pass2<<<DINNER * DSTATE / 256, 256>>>(A_log);
    scan_pass3<<<dim3(DINNER / 8, NC), 256>>>(A_log, Dp);

    // 7. out = y @ Wout^T + x  [2048 x 512 x 1024]  HMMA + resid
    mma_gemm<64, 128, 1, false><<<dim3(4, 32), 256, smem_g4>>>(
        p_y, DINNER, Wout, DINNER, out, DMODEL, SEQ, DMODEL, DINNER, x);
}